// round 4
// baseline (speedup 1.0000x reference)
#include <cuda_runtime.h>
#include <cstdint>

// ---------------------------------------------------------------------------
// Fastformer — tf32 mma.sync GEMMs with ldmatrix fragments, B in [n][k].
// ---------------------------------------------------------------------------

#define Bc 8
#define Sc 2048
#define Dc 1024
#define Hc 16
#define DHc 64
#define Mc (Bc * Sc)   // 16384

__device__ float g_Q[Mc * Dc];         // GEMM1 out fp32
__device__ float g_K[Mc * Dc];         // GEMM2 out fp32
__device__ float g_Qtf[Mc * Dc];       // GEMM1 out, tf32-rounded (GEMM3 A)
__device__ float g_Qseq_tf[Mc * Dc];
__device__ float g_Kseq_tf[Mc * Dc];
__device__ float g_WQt[Dc * Dc];       // transposed+tf32 weights: [n][k]
__device__ float g_WKt[Dc * Dc];
__device__ float g_WP8[Bc * Dc * Dc];  // per-batch kg-scaled WP, [n][k]
__device__ float g_logA[Bc * Hc * Sc];
__device__ float g_logB[Bc * Hc * Sc];
__device__ float g_qg[Bc * Hc * DHc];
__device__ float g_kg[Bc * Dc];

// ===========================================================================
__device__ __forceinline__ uint32_t cvta_smem(const void* p) {
    uint32_t a;
    asm("{ .reg .u64 t; cvta.to.shared.u64 t, %1; cvt.u32.u64 %0, t; }" : "=r"(a) : "l"(p));
    return a;
}
__device__ __forceinline__ uint32_t f2tf(float x) {
    uint32_t u;
    asm("cvt.rna.tf32.f32 %0, %1;" : "=r"(u) : "f"(x));
    return u;
}
__device__ __forceinline__ float tff(float x) { return __uint_as_float(f2tf(x)); }

__device__ __forceinline__ void cp16(uint32_t s, const void* g) {
    asm volatile("cp.async.cg.shared.global [%0], [%1], 16;" :: "r"(s), "l"(g));
}
__device__ __forceinline__ void cp_commit() {
    asm volatile("cp.async.commit_group;" ::: "memory");
}
template <int N>
__device__ __forceinline__ void cp_wait() {
    asm volatile("cp.async.wait_group %0;" :: "n"(N) : "memory");
}
__device__ __forceinline__ void ldmx4(uint32_t& r0, uint32_t& r1, uint32_t& r2, uint32_t& r3,
                                      uint32_t addr) {
    asm volatile("ldmatrix.sync.aligned.m8n8.x4.shared.b16 {%0,%1,%2,%3}, [%4];"
                 : "=r"(r0), "=r"(r1), "=r"(r2), "=r"(r3) : "r"(addr));
}
__device__ __forceinline__ void mma_tf32(float& c0, float& c1, float& c2, float& c3,
                                         uint32_t a0, uint32_t a1, uint32_t a2, uint32_t a3,
                                         uint32_t b0, uint32_t b1) {
    asm volatile(
        "mma.sync.aligned.m16n8k8.row.col.f32.tf32.tf32.f32 "
        "{%0,%1,%2,%3}, {%4,%5,%6,%7}, {%8,%9}, {%0,%1,%2,%3};"
        : "+f"(c0), "+f"(c1), "+f"(c2), "+f"(c3)
        : "r"(a0), "r"(a1), "r"(a2), "r"(a3), "r"(b0), "r"(b1));
}

// ===========================================================================
// GEMM: C[M,N] = A[M,K] @ Bt[N,K]^T   A row-major [m][k], Bt row-major [n][k],
// both tf32-pre-rounded. BM=BN=128, BK=32, 256 thr (8 warps, 2Mx4N),
// 3-stage cp.async, ldmatrix.x4 fragments.
// MODE 0: C.  MODE 1: C + Ctf (rounded copy).  MODE 2: Bt per-batch, +resid.
// ===========================================================================
#define KST 36                      // floats per smem row (32 + 4 pad)
#define TILEB (128 * KST * 4)       // 18432 bytes per matrix tile
#define STGB (2 * TILEB)            // 36864
#define NSTAGE 3
#define GSMEM (NSTAGE * STGB)       // 110592
#define NCH (Dc / 32)               // 32

template <int MODE>
__global__ __launch_bounds__(256, 2)
void gemm_mma(const float* __restrict__ A, const float* __restrict__ Bt,
              float* __restrict__ C, float* __restrict__ Ctf,
              const float* __restrict__ resid)
{
    extern __shared__ char smem[];
    const uint32_t sb = cvta_smem(smem);
    const int tid  = threadIdx.x;
    const int wid  = tid >> 5, lane = tid & 31;
    const int g    = lane >> 2, t = lane & 3;
    const int wm   = wid >> 2, wn = wid & 3;
    const int crow = blockIdx.y * 128, ccol = blockIdx.x * 128;

    if (MODE == 2) Bt += (size_t)(crow / Sc) * Dc * Dc;

    // loaders: 2 threads/row, 64B half each; A rows = m, B rows = n
    const int row = tid >> 1, half = tid & 1;
    const float* Ag = A  + (size_t)(crow + row) * Dc + half * 16;
    const float* Bg = Bt + (size_t)(ccol + row) * Dc + half * 16;
    const uint32_t sA = (uint32_t)(row * 144 + half * 64);
    const uint32_t sB = (uint32_t)(TILEB + row * 144 + half * 64);

    // ldmatrix per-lane offsets
    const int ltile = lane >> 3, lr = lane & 7;
    uint32_t offA[4], offB[2];
#pragma unroll
    for (int im = 0; im < 4; im++)
        offA[im] = (uint32_t)((wm * 64 + im * 16 + (ltile & 1) * 8 + lr) * 144 + (ltile >> 1) * 16);
#pragma unroll
    for (int j = 0; j < 2; j++)
        offB[j] = (uint32_t)(TILEB + (wn * 32 + j * 16 + (ltile & 1) * 8 + lr) * 144 + (ltile >> 1) * 16);

    float acc[4][4][4];
#pragma unroll
    for (int i = 0; i < 4; i++)
#pragma unroll
        for (int j = 0; j < 4; j++)
#pragma unroll
            for (int k = 0; k < 4; k++) acc[i][j][k] = 0.f;

    auto issue = [&](int c) {
        uint32_t base = sb + (uint32_t)(c % NSTAGE) * STGB;
        const float* ag = Ag + c * 32;
        const float* bg = Bg + c * 32;
#pragma unroll
        for (int j = 0; j < 4; j++) cp16(base + sA + j * 16, ag + j * 4);
#pragma unroll
        for (int j = 0; j < 4; j++) cp16(base + sB + j * 16, bg + j * 4);
        cp_commit();
    };

    issue(0);
    issue(1);

    for (int c = 0; c < NCH; c++) {
        if (c + 2 < NCH) cp_wait<1>(); else cp_wait<0>();
        __syncthreads();
        if (c + 2 < NCH) issue(c + 2);

        const uint32_t base = sb + (uint32_t)(c % NSTAGE) * STGB;

#pragma unroll
        for (int kk = 0; kk < 4; kk++) {
            uint32_t a[4][4], b[4][2];
#pragma unroll
            for (int im = 0; im < 4; im++)
                ldmx4(a[im][0], a[im][1], a[im][2], a[im][3], base + offA[im] + kk * 32);
#pragma unroll
            for (int j = 0; j < 2; j++) {
                uint32_t r0, r1, r2, r3;
                ldmx4(r0, r1, r2, r3, base + offB[j] + kk * 32);
                b[2 * j][0] = r0; b[2 * j + 1][0] = r1;
                b[2 * j][1] = r2; b[2 * j + 1][1] = r3;
            }
#pragma unroll
            for (int im = 0; im < 4; im++)
#pragma unroll
                for (int in = 0; in < 4; in++)
                    mma_tf32(acc[im][in][0], acc[im][in][1], acc[im][in][2], acc[im][in][3],
                             a[im][0], a[im][1], a[im][2], a[im][3],
                             b[in][0], b[in][1]);
        }
        __syncthreads();
    }

    // epilogue (fragment layout: rows g, g+8; cols 2t, 2t+1)
#pragma unroll
    for (int im = 0; im < 4; im++) {
#pragma unroll
        for (int in = 0; in < 4; in++) {
            const int r0 = crow + wm * 64 + im * 16 + g;
            const int cc = ccol + wn * 32 + in * 8 + 2 * t;
            float2 v0 = make_float2(acc[im][in][0], acc[im][in][1]);
            float2 v1 = make_float2(acc[im][in][2], acc[im][in][3]);
            if (MODE == 2) {
                float2 q0 = *(const float2*)(resid + (size_t)r0 * Dc + cc);
                float2 q1 = *(const float2*)(resid + (size_t)(r0 + 8) * Dc + cc);
                v0.x += q0.x; v0.y += q0.y; v1.x += q1.x; v1.y += q1.y;
            }
            *(float2*)(C + (size_t)r0 * Dc + cc) = v0;
            *(float2*)(C + (size_t)(r0 + 8) * Dc + cc) = v1;
            if (MODE == 1) {
                *(float2*)(Ctf + (size_t)r0 * Dc + cc) = make_float2(tff(v0.x), tff(v0.y));
                *(float2*)(Ctf + (size_t)(r0 + 8) * Dc + cc) = make_float2(tff(v1.x), tff(v1.y));
            }
        }
    }
}

// ===========================================================================
// elementwise tf32 rounding
// ===========================================================================
__global__ void cvt_tf32_k(const float* __restrict__ in, float* __restrict__ out, int n4)
{
    int i = blockIdx.x * blockDim.x + threadIdx.x;
    if (i >= n4) return;
    float4 v = ((const float4*)in)[i];
    v.x = tff(v.x); v.y = tff(v.y); v.z = tff(v.z); v.w = tff(v.w);
    ((float4*)out)[i] = v;
}

// transpose + tf32 round: Wt[n][k] = rna(W[k][n])
__global__ void tcvt_k(const float* __restrict__ W, float* __restrict__ Wt)
{
    __shared__ float tbuf[32][33];
    int n0 = blockIdx.x * 32, k0 = blockIdx.y * 32;
    int tx = threadIdx.x, ty = threadIdx.y;
#pragma unroll
    for (int i = 0; i < 32; i += 8) tbuf[ty + i][tx] = W[(size_t)(k0 + ty + i) * Dc + n0 + tx];
    __syncthreads();
#pragma unroll
    for (int i = 0; i < 32; i += 8)
        Wt[(size_t)(n0 + ty + i) * Dc + k0 + tx] = tff(tbuf[tx][ty + i]);
}

// per-batch scaled transposed WP: g_WP8[b][n][k] = rna(kg[b,k] * WP[k][n])
__global__ void wp8t_k(const float* __restrict__ WP)
{
    __shared__ float tbuf[32][33];
    int n0 = blockIdx.x * 32, k0 = blockIdx.y * 32, b = blockIdx.z;
    int tx = threadIdx.x, ty = threadIdx.y;
#pragma unroll
    for (int i = 0; i < 32; i += 8)
        tbuf[ty + i][tx] = WP[(size_t)(k0 + ty + i) * Dc + n0 + tx] * g_kg[b * Dc + k0 + ty + i];
    __syncthreads();
    float* outb = g_WP8 + (size_t)b * Dc * Dc;
#pragma unroll
    for (int i = 0; i < 32; i += 8)
        outb[(size_t)(n0 + ty + i) * Dc + k0 + tx] = tff(tbuf[tx][ty + i]);
}

// ===========================================================================
// logitsA: one warp per (b,s)
// ===========================================================================
__global__ void logitsA_k(const float* __restrict__ Wa)
{
    int gw = (blockIdx.x * blockDim.x + threadIdx.x) >> 5;
    if (gw >= Mc) return;
    int lane = threadIdx.x & 31;
    int b = gw >> 11, s = gw & 2047;

    const float* q = g_Q + (size_t)gw * Dc;
    float acc[16];
#pragma unroll
    for (int e = 0; e < 16; e++) acc[e] = 0.f;

    for (int d = lane; d < Dc; d += 32) {
        float qv = q[d];
        const float4* w4 = reinterpret_cast<const float4*>(Wa + d * 16);
        float4 w0 = w4[0], w1 = w4[1], w2 = w4[2], w3 = w4[3];
        acc[0]  += qv * w0.x; acc[1]  += qv * w0.y; acc[2]  += qv * w0.z; acc[3]  += qv * w0.w;
        acc[4]  += qv * w1.x; acc[5]  += qv * w1.y; acc[6]  += qv * w1.z; acc[7]  += qv * w1.w;
        acc[8]  += qv * w2.x; acc[9]  += qv * w2.y; acc[10] += qv * w2.z; acc[11] += qv * w2.w;
        acc[12] += qv * w3.x; acc[13] += qv * w3.y; acc[14] += qv * w3.z; acc[15] += qv * w3.w;
    }
#pragma unroll
    for (int e = 0; e < 16; e++) {
        float v = acc[e];
#pragma unroll
        for (int o = 16; o; o >>= 1) v += __shfl_xor_sync(0xffffffffu, v, o);
        if (lane == e) g_logA[(b * Hc + e) * Sc + s] = v * 0.125f;
    }
}

// ===========================================================================
// logitsB: reshape-scramble gather path
// ===========================================================================
__global__ void logitsB_k(const float* __restrict__ Wb)
{
    int gw = (blockIdx.x * blockDim.x + threadIdx.x) >> 5;
    if (gw >= Mc) return;
    int lane = threadIdx.x & 31;
    int b = gw >> 11, sp = gw & 2047;
    int h0 = sp >> 7, s0 = (sp & 127) << 4;

    const float* qgv = g_qg + (b * Hc + h0) * DHc;
    const float* Kb  = g_K + ((size_t)(b * Sc + s0)) * Dc + h0 * DHc;

    float acc[16];
#pragma unroll
    for (int e = 0; e < 16; e++) acc[e] = 0.f;

    for (int k = lane; k < Dc; k += 32) {
        int tt = k >> 6, j = k & 63;
        float v = Kb[(size_t)tt * Dc + j] * qgv[j];
        const float4* w4 = reinterpret_cast<const float4*>(Wb + k * 16);
        float4 w0 = w4[0], w1 = w4[1], w2 = w4[2], w3 = w4[3];
        acc[0]  += v * w0.x; acc[1]  += v * w0.y; acc[2]  += v * w0.z; acc[3]  += v * w0.w;
        acc[4]  += v * w1.x; acc[5]  += v * w1.y; acc[6]  += v * w1.z; acc[7]  += v * w1.w;
        acc[8]  += v * w2.x; acc[9]  += v * w2.y; acc[10] += v * w2.z; acc[11] += v * w2.w;
        acc[12] += v * w3.x; acc[13] += v * w3.y; acc[14] += v * w3.z; acc[15] += v * w3.w;
    }
#pragma unroll
    for (int e = 0; e < 16; e++) {
        float v = acc[e];
#pragma unroll
        for (int o = 16; o; o >>= 1) v += __shfl_xor_sync(0xffffffffu, v, o);
        if (lane == e) g_logB[(b * Hc + e) * Sc + sp] = v * 0.125f;
    }
}

// ===========================================================================
// pool: one block (512 thr) per (b,h)
// ===========================================================================
__global__ void pool_k(const float* __restrict__ logits, const float* __restrict__ X,
                       const float* __restrict__ qscale, float* __restrict__ out)
{
    int bh = blockIdx.x;
    int b = bh >> 4, h = bh & 15;
    const float* lg = logits + bh * Sc;

    __shared__ float sE[Sc];
    __shared__ float red[16];
    __shared__ float part[8][DHc];

    int tid = threadIdx.x, lane = tid & 31, warp = tid >> 5;

    float mx = -1e30f;
    for (int s = tid; s < Sc; s += 512) mx = fmaxf(mx, lg[s]);
#pragma unroll
    for (int o = 16; o; o >>= 1) mx = fmaxf(mx, __shfl_xor_sync(0xffffffffu, mx, o));
    if (lane == 0) red[warp] = mx;
    __syncthreads();
    mx = red[0];
#pragma unroll
    for (int i = 1; i < 16; i++) mx = fmaxf(mx, red[i]);
    __syncthreads();

    float sum = 0.f;
    for (int s = tid; s < Sc; s += 512) {
        float e = __expf(lg[s] - mx);
        sE[s] = e;
        sum += e;
    }
#pragma unroll
    for (int o = 16; o; o >>= 1) sum += __shfl_xor_sync(0xffffffffu, sum, o);
    if (lane == 0) red[warp] = sum;
    __syncthreads();
    float tot = 0.f;
#pragma unroll
    for (int i = 0; i < 16; i++) tot += red[i];
    float inv = 1.0f / tot;

    int j = tid & 63, gg = tid >> 6;
    const float* Xb = X + ((size_t)b * Sc) * Dc + h * DHc + j;
    float a0 = 0.f, a1 = 0.f, a2 = 0.f, a3 = 0.f;
    for (int s = gg; s < Sc; s += 32) {
        a0 += sE[s]      * Xb[(size_t)s * Dc];
        a1 += sE[s + 8]  * Xb[(size_t)(s + 8)  * Dc];
        a2 += sE[s + 16] * Xb[(size_t)(s + 16) * Dc];
        a3 += sE[s + 24] * Xb[(size_t)(s + 24) * Dc];
    }
    part[gg][j] = (a0 + a1) + (a2 + a3);
    __syncthreads();
    if (gg == 0) {
        float v = 0.f;
#pragma unroll
        for (int i = 0; i < 8; i++) v += part[i][j];
        v *= inv;
        if (qscale) v *= qscale[bh * DHc + j];
        out[bh * DHc + j] = v;
    }
}

// ===========================================================================
extern "C" void kernel_launch(void* const* d_in, const int* in_sizes, int n_in,
                              void* d_out, int out_size)
{
    const float* Qseq = (const float*)d_in[0];
    const float* Kseq = (const float*)d_in[1];
    const float* WQ = (const float*)d_in[3];
    const float* WK = (const float*)d_in[4];
    const float* Wa = (const float*)d_in[5];
    const float* Wb = (const float*)d_in[6];
    const float* WP = (const float*)d_in[7];
    float* out = (float*)d_out;

    float *pQ, *pK, *pQtf, *pQs, *pKs, *pWQ, *pWK, *pWP8, *pLA, *pLB, *pqg, *pkg;
    cudaGetSymbolAddress((void**)&pQ,   g_Q);
    cudaGetSymbolAddress((void**)&pK,   g_K);
    cudaGetSymbolAddress((void**)&pQtf, g_Qtf);
    cudaGetSymbolAddress((void**)&pQs,  g_Qseq_tf);
    cudaGetSymbolAddress((void**)&pKs,  g_Kseq_tf);
    cudaGetSymbolAddress((void**)&pWQ,  g_WQt);
    cudaGetSymbolAddress((void**)&pWK,  g_WKt);
    cudaGetSymbolAddress((void**)&pWP8, g_WP8);
    cudaGetSymbolAddress((void**)&pLA,  g_logA);
    cudaGetSymbolAddress((void**)&pLB,  g_logB);
    cudaGetSymbolAddress((void**)&pqg,  g_qg);
    cudaGetSymbolAddress((void**)&pkg,  g_kg);

    cudaFuncSetAttribute(gemm_mma<0>, cudaFuncAttributeMaxDynamicSharedMemorySize, GSMEM);
    cudaFuncSetAttribute(gemm_mma<1>, cudaFuncAttributeMaxDynamicSharedMemorySize, GSMEM);
    cudaFuncSetAttribute(gemm_mma<2>, cudaFuncAttributeMaxDynamicSharedMemorySize, GSMEM);

    const int big4 = Mc * Dc / 4;
    dim3 tg(32, 32), tb(32, 8);
    dim3 gg(Dc / 128, Mc / 128);

    // launch order chosen so gemm1 is launch #4 (profiled slot)
    tcvt_k<<<tg, tb>>>(WQ, pWQ);                               // 1
    tcvt_k<<<tg, tb>>>(WK, pWK);                               // 2
    cvt_tf32_k<<<(big4 + 255) / 256, 256>>>(Qseq, pQs, big4);  // 3
    gemm_mma<1><<<gg, 256, GSMEM>>>(pQs, pWQ, pQ, pQtf, nullptr);   // 4 <- profiled
    cvt_tf32_k<<<(big4 + 255) / 256, 256>>>(Kseq, pKs, big4);  // 5
    gemm_mma<0><<<gg, 256, GSMEM>>>(pKs, pWK, pK, nullptr, nullptr); // 6

    logitsA_k<<<Mc / 8, 256>>>(Wa);
    pool_k<<<Bc * Hc, 512>>>(pLA, pQ, nullptr, pqg);
    logitsB_k<<<Mc / 8, 256>>>(Wb);
    pool_k<<<Bc * Hc, 512>>>(pLB, pK, pqg, pkg);

    dim3 wg(32, 32, 8);
    wp8t_k<<<wg, tb>>>(WP);
    gemm_mma<2><<<gg, 256, GSMEM>>>(pQtf, pWP8, out, nullptr, pQ);
}

// round 5
// speedup vs baseline: 1.2341x; 1.2341x over previous
#include <cuda_runtime.h>
#include <cstdint>

// ---------------------------------------------------------------------------
// Fastformer — tf32 mma.sync GEMMs, 64x64 warp tiles (low smem redundancy).
// ---------------------------------------------------------------------------

#define Bc 8
#define Sc 2048
#define Dc 1024
#define Hc 16
#define DHc 64
#define Mc (Bc * Sc)   // 16384

__device__ float g_Q[Mc * Dc];
__device__ float g_K[Mc * Dc];
__device__ float g_Qtf[Mc * Dc];
__device__ float g_Qseq_tf[Mc * Dc];
__device__ float g_Kseq_tf[Mc * Dc];
__device__ float g_WQt[Dc * Dc];       // [n][k] transposed+tf32
__device__ float g_WKt[Dc * Dc];
__device__ float g_WP8[Bc * Dc * Dc];  // per-batch kg-scaled WP, [n][k]
__device__ float g_logA[Bc * Hc * Sc];
__device__ float g_logB[Bc * Hc * Sc];
__device__ float g_qg[Bc * Hc * DHc];
__device__ float g_kg[Bc * Dc];

// ===========================================================================
__device__ __forceinline__ uint32_t cvta_smem(const void* p) {
    uint32_t a;
    asm("{ .reg .u64 t; cvta.to.shared.u64 t, %1; cvt.u32.u64 %0, t; }" : "=r"(a) : "l"(p));
    return a;
}
__device__ __forceinline__ uint32_t f2tf(float x) {
    uint32_t u;
    asm("cvt.rna.tf32.f32 %0, %1;" : "=r"(u) : "f"(x));
    return u;
}
__device__ __forceinline__ float tff(float x) { return __uint_as_float(f2tf(x)); }

__device__ __forceinline__ void cp16(uint32_t s, const void* g) {
    asm volatile("cp.async.cg.shared.global [%0], [%1], 16;" :: "r"(s), "l"(g));
}
__device__ __forceinline__ void cp_commit() {
    asm volatile("cp.async.commit_group;" ::: "memory");
}
template <int N>
__device__ __forceinline__ void cp_wait() {
    asm volatile("cp.async.wait_group %0;" :: "n"(N) : "memory");
}
__device__ __forceinline__ void ldmx4(uint32_t& r0, uint32_t& r1, uint32_t& r2, uint32_t& r3,
                                      uint32_t addr) {
    asm volatile("ldmatrix.sync.aligned.m8n8.x4.shared.b16 {%0,%1,%2,%3}, [%4];"
                 : "=r"(r0), "=r"(r1), "=r"(r2), "=r"(r3) : "r"(addr));
}
__device__ __forceinline__ void mma_tf32(float& c0, float& c1, float& c2, float& c3,
                                         uint32_t a0, uint32_t a1, uint32_t a2, uint32_t a3,
                                         uint32_t b0, uint32_t b1) {
    asm volatile(
        "mma.sync.aligned.m16n8k8.row.col.f32.tf32.tf32.f32 "
        "{%0,%1,%2,%3}, {%4,%5,%6,%7}, {%8,%9}, {%0,%1,%2,%3};"
        : "+f"(c0), "+f"(c1), "+f"(c2), "+f"(c3)
        : "r"(a0), "r"(a1), "r"(a2), "r"(a3), "r"(b0), "r"(b1));
}

// ===========================================================================
// GEMM: C[M,N] = A[M,K] @ Bt[N,K]^T.  BM=BN=128, BK=32, 128 thr (4 warps,
// 2x2 grid of 64x64 warp tiles), 3-stage cp.async, ldmatrix.x4, 1 sync/chunk.
// MODE 0: C.  MODE 1: C + Ctf.  MODE 2: Bt per-batch, +resid.
// ===========================================================================
#define TILEB (128 * 144)           // bytes per matrix tile (row stride 144B)
#define STGB (2 * TILEB)            // 36864
#define NSTAGE 3
#define GSMEM (NSTAGE * STGB)       // 110592
#define NCH (Dc / 32)               // 32

template <int MODE>
__global__ __launch_bounds__(128, 2)
void gemm_mma(const float* __restrict__ A, const float* __restrict__ Bt,
              float* __restrict__ C, float* __restrict__ Ctf,
              const float* __restrict__ resid)
{
    extern __shared__ char smem[];
    const uint32_t sb = cvta_smem(smem);
    const int tid  = threadIdx.x;
    const int wid  = tid >> 5, lane = tid & 31;
    const int g    = lane >> 2, t = lane & 3;
    const int wm   = wid >> 1, wn = wid & 1;       // 2x2 warp grid
    const int crow = blockIdx.y * 128, ccol = blockIdx.x * 128;

    if (MODE == 2) Bt += (size_t)(crow / Sc) * Dc * Dc;

    // loaders: 8 threads/row (16B each); 16 rows per pass, 8 passes
    const int lrow = tid >> 3, seg = tid & 7;
    const float* Ag = A  + (size_t)(crow + lrow) * Dc + seg * 4;
    const float* Bg = Bt + (size_t)(ccol + lrow) * Dc + seg * 4;
    const uint32_t sA = (uint32_t)(lrow * 144 + seg * 16);
    const uint32_t sB = (uint32_t)(TILEB + lrow * 144 + seg * 16);

    // ldmatrix per-lane offsets
    const int ltile = lane >> 3, lr = lane & 7;
    uint32_t offA[4], offB[4];
#pragma unroll
    for (int im = 0; im < 4; im++)
        offA[im] = (uint32_t)((wm * 64 + im * 16 + (ltile & 1) * 8 + lr) * 144 + (ltile >> 1) * 16);
#pragma unroll
    for (int j = 0; j < 4; j++)
        offB[j] = (uint32_t)(TILEB + (wn * 64 + j * 16 + (ltile & 1) * 8 + lr) * 144 + (ltile >> 1) * 16);

    float acc[4][8][4];
#pragma unroll
    for (int i = 0; i < 4; i++)
#pragma unroll
        for (int j = 0; j < 8; j++)
#pragma unroll
            for (int k = 0; k < 4; k++) acc[i][j][k] = 0.f;

    auto issue = [&](int c) {
        uint32_t base = sb + (uint32_t)(c % NSTAGE) * STGB;
        const float* ag = Ag + c * 32;
        const float* bg = Bg + c * 32;
#pragma unroll
        for (int rr = 0; rr < 8; rr++) {
            cp16(base + sA + rr * (16 * 144), ag + (size_t)rr * 16 * Dc);
            cp16(base + sB + rr * (16 * 144), bg + (size_t)rr * 16 * Dc);
        }
        cp_commit();
    };

    issue(0);
    issue(1);

    for (int c = 0; c < NCH; c++) {
        if (c + 2 < NCH) cp_wait<1>(); else cp_wait<0>();
        __syncthreads();
        if (c + 2 < NCH) issue(c + 2);   // slot (c-1)%3, drained by the sync

        const uint32_t base = sb + (uint32_t)(c % NSTAGE) * STGB;

#pragma unroll
        for (int kk = 0; kk < 4; kk++) {
            uint32_t a[4][4], b[8][2];
#pragma unroll
            for (int im = 0; im < 4; im++)
                ldmx4(a[im][0], a[im][1], a[im][2], a[im][3], base + offA[im] + kk * 32);
#pragma unroll
            for (int j = 0; j < 4; j++) {
                uint32_t r0, r1, r2, r3;
                ldmx4(r0, r1, r2, r3, base + offB[j] + kk * 32);
                b[2 * j][0] = r0; b[2 * j + 1][0] = r1;
                b[2 * j][1] = r2; b[2 * j + 1][1] = r3;
            }
#pragma unroll
            for (int im = 0; im < 4; im++)
#pragma unroll
                for (int in = 0; in < 8; in++)
                    mma_tf32(acc[im][in][0], acc[im][in][1], acc[im][in][2], acc[im][in][3],
                             a[im][0], a[im][1], a[im][2], a[im][3],
                             b[in][0], b[in][1]);
        }
    }
    __syncthreads();

    // epilogue (fragment rows g, g+8; cols 2t, 2t+1)
#pragma unroll
    for (int im = 0; im < 4; im++) {
#pragma unroll
        for (int in = 0; in < 8; in++) {
            const int r0 = crow + wm * 64 + im * 16 + g;
            const int cc = ccol + wn * 64 + in * 8 + 2 * t;
            float2 v0 = make_float2(acc[im][in][0], acc[im][in][1]);
            float2 v1 = make_float2(acc[im][in][2], acc[im][in][3]);
            if (MODE == 2) {
                float2 q0 = *(const float2*)(resid + (size_t)r0 * Dc + cc);
                float2 q1 = *(const float2*)(resid + (size_t)(r0 + 8) * Dc + cc);
                v0.x += q0.x; v0.y += q0.y; v1.x += q1.x; v1.y += q1.y;
            }
            *(float2*)(C + (size_t)r0 * Dc + cc) = v0;
            *(float2*)(C + (size_t)(r0 + 8) * Dc + cc) = v1;
            if (MODE == 1) {
                *(float2*)(Ctf + (size_t)r0 * Dc + cc) = make_float2(tff(v0.x), tff(v0.y));
                *(float2*)(Ctf + (size_t)(r0 + 8) * Dc + cc) = make_float2(tff(v1.x), tff(v1.y));
            }
        }
    }
}

// ===========================================================================
__global__ void cvt_tf32_k(const float* __restrict__ in, float* __restrict__ out, int n4)
{
    int i = blockIdx.x * blockDim.x + threadIdx.x;
    if (i >= n4) return;
    float4 v = ((const float4*)in)[i];
    v.x = tff(v.x); v.y = tff(v.y); v.z = tff(v.z); v.w = tff(v.w);
    ((float4*)out)[i] = v;
}

__global__ void tcvt_k(const float* __restrict__ W, float* __restrict__ Wt)
{
    __shared__ float tbuf[32][33];
    int n0 = blockIdx.x * 32, k0 = blockIdx.y * 32;
    int tx = threadIdx.x, ty = threadIdx.y;
#pragma unroll
    for (int i = 0; i < 32; i += 8) tbuf[ty + i][tx] = W[(size_t)(k0 + ty + i) * Dc + n0 + tx];
    __syncthreads();
#pragma unroll
    for (int i = 0; i < 32; i += 8)
        Wt[(size_t)(n0 + ty + i) * Dc + k0 + tx] = tff(tbuf[tx][ty + i]);
}

__global__ void wp8t_k(const float* __restrict__ WP)
{
    __shared__ float tbuf[32][33];
    int n0 = blockIdx.x * 32, k0 = blockIdx.y * 32, b = blockIdx.z;
    int tx = threadIdx.x, ty = threadIdx.y;
#pragma unroll
    for (int i = 0; i < 32; i += 8)
        tbuf[ty + i][tx] = WP[(size_t)(k0 + ty + i) * Dc + n0 + tx] * g_kg[b * Dc + k0 + ty + i];
    __syncthreads();
    float* outb = g_WP8 + (size_t)b * Dc * Dc;
#pragma unroll
    for (int i = 0; i < 32; i += 8)
        outb[(size_t)(n0 + ty + i) * Dc + k0 + tx] = tff(tbuf[tx][ty + i]);
}

// ===========================================================================
__global__ void logitsA_k(const float* __restrict__ Wa)
{
    int gw = (blockIdx.x * blockDim.x + threadIdx.x) >> 5;
    if (gw >= Mc) return;
    int lane = threadIdx.x & 31;
    int b = gw >> 11, s = gw & 2047;

    const float* q = g_Q + (size_t)gw * Dc;
    float acc[16];
#pragma unroll
    for (int e = 0; e < 16; e++) acc[e] = 0.f;

    for (int d = lane; d < Dc; d += 32) {
        float qv = q[d];
        const float4* w4 = reinterpret_cast<const float4*>(Wa + d * 16);
        float4 w0 = w4[0], w1 = w4[1], w2 = w4[2], w3 = w4[3];
        acc[0]  += qv * w0.x; acc[1]  += qv * w0.y; acc[2]  += qv * w0.z; acc[3]  += qv * w0.w;
        acc[4]  += qv * w1.x; acc[5]  += qv * w1.y; acc[6]  += qv * w1.z; acc[7]  += qv * w1.w;
        acc[8]  += qv * w2.x; acc[9]  += qv * w2.y; acc[10] += qv * w2.z; acc[11] += qv * w2.w;
        acc[12] += qv * w3.x; acc[13] += qv * w3.y; acc[14] += qv * w3.z; acc[15] += qv * w3.w;
    }
#pragma unroll
    for (int e = 0; e < 16; e++) {
        float v = acc[e];
#pragma unroll
        for (int o = 16; o; o >>= 1) v += __shfl_xor_sync(0xffffffffu, v, o);
        if (lane == e) g_logA[(b * Hc + e) * Sc + s] = v * 0.125f;
    }
}

__global__ void logitsB_k(const float* __restrict__ Wb)
{
    int gw = (blockIdx.x * blockDim.x + threadIdx.x) >> 5;
    if (gw >= Mc) return;
    int lane = threadIdx.x & 31;
    int b = gw >> 11, sp = gw & 2047;
    int h0 = sp >> 7, s0 = (sp & 127) << 4;

    const float* qgv = g_qg + (b * Hc + h0) * DHc;
    const float* Kb  = g_K + ((size_t)(b * Sc + s0)) * Dc + h0 * DHc;

    float acc[16];
#pragma unroll
    for (int e = 0; e < 16; e++) acc[e] = 0.f;

    for (int k = lane; k < Dc; k += 32) {
        int tt = k >> 6, j = k & 63;
        float v = Kb[(size_t)tt * Dc + j] * qgv[j];
        const float4* w4 = reinterpret_cast<const float4*>(Wb + k * 16);
        float4 w0 = w4[0], w1 = w4[1], w2 = w4[2], w3 = w4[3];
        acc[0]  += v * w0.x; acc[1]  += v * w0.y; acc[2]  += v * w0.z; acc[3]  += v * w0.w;
        acc[4]  += v * w1.x; acc[5]  += v * w1.y; acc[6]  += v * w1.z; acc[7]  += v * w1.w;
        acc[8]  += v * w2.x; acc[9]  += v * w2.y; acc[10] += v * w2.z; acc[11] += v * w2.w;
        acc[12] += v * w3.x; acc[13] += v * w3.y; acc[14] += v * w3.z; acc[15] += v * w3.w;
    }
#pragma unroll
    for (int e = 0; e < 16; e++) {
        float v = acc[e];
#pragma unroll
        for (int o = 16; o; o >>= 1) v += __shfl_xor_sync(0xffffffffu, v, o);
        if (lane == e) g_logB[(b * Hc + e) * Sc + sp] = v * 0.125f;
    }
}

// ===========================================================================
__global__ void pool_k(const float* __restrict__ logits, const float* __restrict__ X,
                       const float* __restrict__ qscale, float* __restrict__ out)
{
    int bh = blockIdx.x;
    int b = bh >> 4, h = bh & 15;
    const float* lg = logits + bh * Sc;

    __shared__ float sE[Sc];
    __shared__ float red[16];
    __shared__ float part[8][DHc];

    int tid = threadIdx.x, lane = tid & 31, warp = tid >> 5;

    float mx = -1e30f;
    for (int s = tid; s < Sc; s += 512) mx = fmaxf(mx, lg[s]);
#pragma unroll
    for (int o = 16; o; o >>= 1) mx = fmaxf(mx, __shfl_xor_sync(0xffffffffu, mx, o));
    if (lane == 0) red[warp] = mx;
    __syncthreads();
    mx = red[0];
#pragma unroll
    for (int i = 1; i < 16; i++) mx = fmaxf(mx, red[i]);
    __syncthreads();

    float sum = 0.f;
    for (int s = tid; s < Sc; s += 512) {
        float e = __expf(lg[s] - mx);
        sE[s] = e;
        sum += e;
    }
#pragma unroll
    for (int o = 16; o; o >>= 1) sum += __shfl_xor_sync(0xffffffffu, sum, o);
    if (lane == 0) red[warp] = sum;
    __syncthreads();
    float tot = 0.f;
#pragma unroll
    for (int i = 0; i < 16; i++) tot += red[i];
    float inv = 1.0f / tot;

    int j = tid & 63, gg = tid >> 6;
    const float* Xb = X + ((size_t)b * Sc) * Dc + h * DHc + j;
    float a0 = 0.f, a1 = 0.f, a2 = 0.f, a3 = 0.f;
    for (int s = gg; s < Sc; s += 32) {
        a0 += sE[s]      * Xb[(size_t)s * Dc];
        a1 += sE[s + 8]  * Xb[(size_t)(s + 8)  * Dc];
        a2 += sE[s + 16] * Xb[(size_t)(s + 16) * Dc];
        a3 += sE[s + 24] * Xb[(size_t)(s + 24) * Dc];
    }
    part[gg][j] = (a0 + a1) + (a2 + a3);
    __syncthreads();
    if (gg == 0) {
        float v = 0.f;
#pragma unroll
        for (int i = 0; i < 8; i++) v += part[i][j];
        v *= inv;
        if (qscale) v *= qscale[bh * DHc + j];
        out[bh * DHc + j] = v;
    }
}

// ===========================================================================
extern "C" void kernel_launch(void* const* d_in, const int* in_sizes, int n_in,
                              void* d_out, int out_size)
{
    const float* Qseq = (const float*)d_in[0];
    const float* Kseq = (const float*)d_in[1];
    const float* WQ = (const float*)d_in[3];
    const float* WK = (const float*)d_in[4];
    const float* Wa = (const float*)d_in[5];
    const float* Wb = (const float*)d_in[6];
    const float* WP = (const float*)d_in[7];
    float* out = (float*)d_out;

    float *pQ, *pK, *pQtf, *pQs, *pKs, *pWQ, *pWK, *pWP8, *pLA, *pLB, *pqg, *pkg;
    cudaGetSymbolAddress((void**)&pQ,   g_Q);
    cudaGetSymbolAddress((void**)&pK,   g_K);
    cudaGetSymbolAddress((void**)&pQtf, g_Qtf);
    cudaGetSymbolAddress((void**)&pQs,  g_Qseq_tf);
    cudaGetSymbolAddress((void**)&pKs,  g_Kseq_tf);
    cudaGetSymbolAddress((void**)&pWQ,  g_WQt);
    cudaGetSymbolAddress((void**)&pWK,  g_WKt);
    cudaGetSymbolAddress((void**)&pWP8, g_WP8);
    cudaGetSymbolAddress((void**)&pLA,  g_logA);
    cudaGetSymbolAddress((void**)&pLB,  g_logB);
    cudaGetSymbolAddress((void**)&pqg,  g_qg);
    cudaGetSymbolAddress((void**)&pkg,  g_kg);

    cudaFuncSetAttribute(gemm_mma<0>, cudaFuncAttributeMaxDynamicSharedMemorySize, GSMEM);
    cudaFuncSetAttribute(gemm_mma<1>, cudaFuncAttributeMaxDynamicSharedMemorySize, GSMEM);
    cudaFuncSetAttribute(gemm_mma<2>, cudaFuncAttributeMaxDynamicSharedMemorySize, GSMEM);

    const int big4 = Mc * Dc / 4;
    dim3 tg(32, 32), tb(32, 8);
    dim3 gg(Dc / 128, Mc / 128);

    // gemm1 kept at launch slot 4 (profiled slot)
    tcvt_k<<<tg, tb>>>(WQ, pWQ);                               // 1
    tcvt_k<<<tg, tb>>>(WK, pWK);                               // 2
    cvt_tf32_k<<<(big4 + 255) / 256, 256>>>(Qseq, pQs, big4);  // 3
    gemm_mma<1><<<gg, 128, GSMEM>>>(pQs, pWQ, pQ, pQtf, nullptr);    // 4 <- profiled
    cvt_tf32_k<<<(big4 + 255) / 256, 256>>>(Kseq, pKs, big4);  // 5
    gemm_mma<0><<<gg, 128, GSMEM>>>(pKs, pWK, pK, nullptr, nullptr); // 6

    logitsA_k<<<Mc / 8, 256>>>(Wa);
    pool_k<<<Bc * Hc, 512>>>(pLA, pQ, nullptr, pqg);
    logitsB_k<<<Mc / 8, 256>>>(Wb);
    pool_k<<<Bc * Hc, 512>>>(pLB, pK, pqg, pkg);

    dim3 wg(32, 32, 8);
    wp8t_k<<<wg, tb>>>(WP);
    gemm_mma<2><<<gg, 128, GSMEM>>>(pQtf, pWP8, out, nullptr, pQ);
}

// round 6
// speedup vs baseline: 1.2660x; 1.0258x over previous
#include <cuda_runtime.h>
#include <cstdint>

// ---------------------------------------------------------------------------
// Fastformer — tf32 mma.sync GEMMs, 64x64 warp tiles, double-buffered frags,
// A-side tf32 rounding fused into the GEMM mainloop.
// ---------------------------------------------------------------------------

#define Bc 8
#define Sc 2048
#define Dc 1024
#define Hc 16
#define DHc 64
#define Mc (Bc * Sc)   // 16384

__device__ float g_Q[Mc * Dc];
__device__ float g_K[Mc * Dc];
__device__ float g_Qtf[Mc * Dc];
__device__ float g_WQt[Dc * Dc];       // [n][k] transposed+tf32
__device__ float g_WKt[Dc * Dc];
__device__ float g_WP8[Bc * Dc * Dc];  // per-batch kg-scaled WP, [n][k]
__device__ float g_logA[Bc * Hc * Sc];
__device__ float g_logB[Bc * Hc * Sc];
__device__ float g_qg[Bc * Hc * DHc];
__device__ float g_kg[Bc * Dc];

// ===========================================================================
__device__ __forceinline__ uint32_t cvta_smem(const void* p) {
    uint32_t a;
    asm("{ .reg .u64 t; cvta.to.shared.u64 t, %1; cvt.u32.u64 %0, t; }" : "=r"(a) : "l"(p));
    return a;
}
__device__ __forceinline__ uint32_t f2tf(float x) {
    uint32_t u;
    asm("cvt.rna.tf32.f32 %0, %1;" : "=r"(u) : "f"(x));
    return u;
}
__device__ __forceinline__ float tff(float x) { return __uint_as_float(f2tf(x)); }

__device__ __forceinline__ void cp16(uint32_t s, const void* g) {
    asm volatile("cp.async.cg.shared.global [%0], [%1], 16;" :: "r"(s), "l"(g));
}
__device__ __forceinline__ void cp_commit() {
    asm volatile("cp.async.commit_group;" ::: "memory");
}
template <int N>
__device__ __forceinline__ void cp_wait() {
    asm volatile("cp.async.wait_group %0;" :: "n"(N) : "memory");
}
__device__ __forceinline__ void ldmx4(uint32_t& r0, uint32_t& r1, uint32_t& r2, uint32_t& r3,
                                      uint32_t addr) {
    asm volatile("ldmatrix.sync.aligned.m8n8.x4.shared.b16 {%0,%1,%2,%3}, [%4];"
                 : "=r"(r0), "=r"(r1), "=r"(r2), "=r"(r3) : "r"(addr));
}
__device__ __forceinline__ void mma_tf32(float& c0, float& c1, float& c2, float& c3,
                                         uint32_t a0, uint32_t a1, uint32_t a2, uint32_t a3,
                                         uint32_t b0, uint32_t b1) {
    asm volatile(
        "mma.sync.aligned.m16n8k8.row.col.f32.tf32.tf32.f32 "
        "{%0,%1,%2,%3}, {%4,%5,%6,%7}, {%8,%9}, {%0,%1,%2,%3};"
        : "+f"(c0), "+f"(c1), "+f"(c2), "+f"(c3)
        : "r"(a0), "r"(a1), "r"(a2), "r"(a3), "r"(b0), "r"(b1));
}

// ===========================================================================
// GEMM: C[M,N] = A[M,K] @ Bt[N,K]^T.  BM=BN=128, BK=32, 128 thr (2x2 warps,
// 64x64 tiles), 3-stage cp.async, ldmatrix.x4, double-buffered fragments.
// MODE 0: A raw fp32 (cvt in-reg), store C.
// MODE 1: like 0, plus Ctf (tf32-rounded copy of C).
// MODE 2: A pre-rounded, Bt per-batch, epilogue += resid.
// ===========================================================================
#define TILEB (128 * 144)           // bytes per matrix tile (row stride 144B)
#define STGB (2 * TILEB)            // 36864
#define NSTAGE 3
#define GSMEM (NSTAGE * STGB)       // 110592
#define NCH (Dc / 32)               // 32

template <int MODE>
__global__ __launch_bounds__(128, 2)
void gemm_mma(const float* __restrict__ A, const float* __restrict__ Bt,
              float* __restrict__ C, float* __restrict__ Ctf,
              const float* __restrict__ resid)
{
    constexpr bool CVTA = (MODE != 2);
    extern __shared__ char smem[];
    const uint32_t sb = cvta_smem(smem);
    const int tid  = threadIdx.x;
    const int wid  = tid >> 5, lane = tid & 31;
    const int g    = lane >> 2, t = lane & 3;
    const int wm   = wid >> 1, wn = wid & 1;
    const int crow = blockIdx.y * 128, ccol = blockIdx.x * 128;

    if (MODE == 2) Bt += (size_t)(crow / Sc) * Dc * Dc;

    // loaders: 8 threads/row (16B each); 16 rows per pass, 8 passes
    const int lrow = tid >> 3, seg = tid & 7;
    const float* Ag = A  + (size_t)(crow + lrow) * Dc + seg * 4;
    const float* Bg = Bt + (size_t)(ccol + lrow) * Dc + seg * 4;
    const uint32_t sA = (uint32_t)(lrow * 144 + seg * 16);
    const uint32_t sB = (uint32_t)(TILEB + lrow * 144 + seg * 16);

    // ldmatrix per-lane offsets
    const int ltile = lane >> 3, lr = lane & 7;
    uint32_t offA[4], offB[4];
#pragma unroll
    for (int im = 0; im < 4; im++)
        offA[im] = (uint32_t)((wm * 64 + im * 16 + (ltile & 1) * 8 + lr) * 144 + (ltile >> 1) * 16);
#pragma unroll
    for (int j = 0; j < 4; j++)
        offB[j] = (uint32_t)(TILEB + (wn * 64 + j * 16 + (ltile & 1) * 8 + lr) * 144 + (ltile >> 1) * 16);

    float acc[4][8][4];
#pragma unroll
    for (int i = 0; i < 4; i++)
#pragma unroll
        for (int j = 0; j < 8; j++)
#pragma unroll
            for (int k = 0; k < 4; k++) acc[i][j][k] = 0.f;

    auto issue = [&](int c) {
        uint32_t base = sb + (uint32_t)(c % NSTAGE) * STGB;
        const float* ag = Ag + c * 32;
        const float* bg = Bg + c * 32;
#pragma unroll
        for (int rr = 0; rr < 8; rr++) {
            cp16(base + sA + rr * (16 * 144), ag + (size_t)rr * 16 * Dc);
            cp16(base + sB + rr * (16 * 144), bg + (size_t)rr * 16 * Dc);
        }
        cp_commit();
    };

    uint32_t a[2][4][4], b[2][8][2];

    auto ldfrags = [&](uint32_t base, int kk, int bi) {
#pragma unroll
        for (int im = 0; im < 4; im++)
            ldmx4(a[bi][im][0], a[bi][im][1], a[bi][im][2], a[bi][im][3],
                  base + offA[im] + kk * 32);
#pragma unroll
        for (int j = 0; j < 4; j++) {
            uint32_t r0, r1, r2, r3;
            ldmx4(r0, r1, r2, r3, base + offB[j] + kk * 32);
            b[bi][2 * j][0] = r0; b[bi][2 * j + 1][0] = r1;
            b[bi][2 * j][1] = r2; b[bi][2 * j + 1][1] = r3;
        }
    };
    auto cvtA = [&](int bi) {
        if (CVTA) {
#pragma unroll
            for (int im = 0; im < 4; im++)
#pragma unroll
                for (int r = 0; r < 4; r++)
                    a[bi][im][r] = f2tf(__uint_as_float(a[bi][im][r]));
        }
    };

    issue(0);
    issue(1);

    for (int c = 0; c < NCH; c++) {
        if (c + 2 < NCH) cp_wait<1>(); else cp_wait<0>();
        __syncthreads();
        if (c + 2 < NCH) issue(c + 2);

        const uint32_t base = sb + (uint32_t)(c % NSTAGE) * STGB;

        ldfrags(base, 0, 0);
        cvtA(0);
#pragma unroll
        for (int kk = 0; kk < 4; kk++) {
            const int cur = kk & 1, nxt = cur ^ 1;
            if (kk < 3) ldfrags(base, kk + 1, nxt);
#pragma unroll
            for (int im = 0; im < 4; im++)
#pragma unroll
                for (int in = 0; in < 8; in++)
                    mma_tf32(acc[im][in][0], acc[im][in][1], acc[im][in][2], acc[im][in][3],
                             a[cur][im][0], a[cur][im][1], a[cur][im][2], a[cur][im][3],
                             b[cur][in][0], b[cur][in][1]);
            if (kk < 3) cvtA(nxt);
        }
    }
    __syncthreads();

    // epilogue (fragment rows g, g+8; cols 2t, 2t+1)
#pragma unroll
    for (int im = 0; im < 4; im++) {
#pragma unroll
        for (int in = 0; in < 8; in++) {
            const int r0 = crow + wm * 64 + im * 16 + g;
            const int cc = ccol + wn * 64 + in * 8 + 2 * t;
            float2 v0 = make_float2(acc[im][in][0], acc[im][in][1]);
            float2 v1 = make_float2(acc[im][in][2], acc[im][in][3]);
            if (MODE == 2) {
                float2 q0 = *(const float2*)(resid + (size_t)r0 * Dc + cc);
                float2 q1 = *(const float2*)(resid + (size_t)(r0 + 8) * Dc + cc);
                v0.x += q0.x; v0.y += q0.y; v1.x += q1.x; v1.y += q1.y;
            }
            *(float2*)(C + (size_t)r0 * Dc + cc) = v0;
            *(float2*)(C + (size_t)(r0 + 8) * Dc + cc) = v1;
            if (MODE == 1) {
                *(float2*)(Ctf + (size_t)r0 * Dc + cc) = make_float2(tff(v0.x), tff(v0.y));
                *(float2*)(Ctf + (size_t)(r0 + 8) * Dc + cc) = make_float2(tff(v1.x), tff(v1.y));
            }
        }
    }
}

// ===========================================================================
__global__ void tcvt_k(const float* __restrict__ W, float* __restrict__ Wt)
{
    __shared__ float tbuf[32][33];
    int n0 = blockIdx.x * 32, k0 = blockIdx.y * 32;
    int tx = threadIdx.x, ty = threadIdx.y;
#pragma unroll
    for (int i = 0; i < 32; i += 8) tbuf[ty + i][tx] = W[(size_t)(k0 + ty + i) * Dc + n0 + tx];
    __syncthreads();
#pragma unroll
    for (int i = 0; i < 32; i += 8)
        Wt[(size_t)(n0 + ty + i) * Dc + k0 + tx] = tff(tbuf[tx][ty + i]);
}

__global__ void wp8t_k(const float* __restrict__ WP)
{
    __shared__ float tbuf[32][33];
    int n0 = blockIdx.x * 32, k0 = blockIdx.y * 32, b = blockIdx.z;
    int tx = threadIdx.x, ty = threadIdx.y;
#pragma unroll
    for (int i = 0; i < 32; i += 8)
        tbuf[ty + i][tx] = WP[(size_t)(k0 + ty + i) * Dc + n0 + tx] * g_kg[b * Dc + k0 + ty + i];
    __syncthreads();
    float* outb = g_WP8 + (size_t)b * Dc * Dc;
#pragma unroll
    for (int i = 0; i < 32; i += 8)
        outb[(size_t)(n0 + ty + i) * Dc + k0 + tx] = tff(tbuf[tx][ty + i]);
}

// ===========================================================================
__global__ void logitsA_k(const float* __restrict__ Wa)
{
    int gw = (blockIdx.x * blockDim.x + threadIdx.x) >> 5;
    if (gw >= Mc) return;
    int lane = threadIdx.x & 31;
    int b = gw >> 11, s = gw & 2047;

    const float* q = g_Q + (size_t)gw * Dc;
    float acc[16];
#pragma unroll
    for (int e = 0; e < 16; e++) acc[e] = 0.f;

    for (int d = lane; d < Dc; d += 32) {
        float qv = q[d];
        const float4* w4 = reinterpret_cast<const float4*>(Wa + d * 16);
        float4 w0 = w4[0], w1 = w4[1], w2 = w4[2], w3 = w4[3];
        acc[0]  += qv * w0.x; acc[1]  += qv * w0.y; acc[2]  += qv * w0.z; acc[3]  += qv * w0.w;
        acc[4]  += qv * w1.x; acc[5]  += qv * w1.y; acc[6]  += qv * w1.z; acc[7]  += qv * w1.w;
        acc[8]  += qv * w2.x; acc[9]  += qv * w2.y; acc[10] += qv * w2.z; acc[11] += qv * w2.w;
        acc[12] += qv * w3.x; acc[13] += qv * w3.y; acc[14] += qv * w3.z; acc[15] += qv * w3.w;
    }
#pragma unroll
    for (int e = 0; e < 16; e++) {
        float v = acc[e];
#pragma unroll
        for (int o = 16; o; o >>= 1) v += __shfl_xor_sync(0xffffffffu, v, o);
        if (lane == e) g_logA[(b * Hc + e) * Sc + s] = v * 0.125f;
    }
}

__global__ void logitsB_k(const float* __restrict__ Wb)
{
    int gw = (blockIdx.x * blockDim.x + threadIdx.x) >> 5;
    if (gw >= Mc) return;
    int lane = threadIdx.x & 31;
    int b = gw >> 11, sp = gw & 2047;
    int h0 = sp >> 7, s0 = (sp & 127) << 4;

    const float* qgv = g_qg + (b * Hc + h0) * DHc;
    const float* Kb  = g_K + ((size_t)(b * Sc + s0)) * Dc + h0 * DHc;

    float acc[16];
#pragma unroll
    for (int e = 0; e < 16; e++) acc[e] = 0.f;

    for (int k = lane; k < Dc; k += 32) {
        int tt = k >> 6, j = k & 63;
        float v = Kb[(size_t)tt * Dc + j] * qgv[j];
        const float4* w4 = reinterpret_cast<const float4*>(Wb + k * 16);
        float4 w0 = w4[0], w1 = w4[1], w2 = w4[2], w3 = w4[3];
        acc[0]  += v * w0.x; acc[1]  += v * w0.y; acc[2]  += v * w0.z; acc[3]  += v * w0.w;
        acc[4]  += v * w1.x; acc[5]  += v * w1.y; acc[6]  += v * w1.z; acc[7]  += v * w1.w;
        acc[8]  += v * w2.x; acc[9]  += v * w2.y; acc[10] += v * w2.z; acc[11] += v * w2.w;
        acc[12] += v * w3.x; acc[13] += v * w3.y; acc[14] += v * w3.z; acc[15] += v * w3.w;
    }
#pragma unroll
    for (int e = 0; e < 16; e++) {
        float v = acc[e];
#pragma unroll
        for (int o = 16; o; o >>= 1) v += __shfl_xor_sync(0xffffffffu, v, o);
        if (lane == e) g_logB[(b * Hc + e) * Sc + sp] = v * 0.125f;
    }
}

// ===========================================================================
__global__ void pool_k(const float* __restrict__ logits, const float* __restrict__ X,
                       const float* __restrict__ qscale, float* __restrict__ out)
{
    int bh = blockIdx.x;
    int b = bh >> 4, h = bh & 15;
    const float* lg = logits + bh * Sc;

    __shared__ float sE[Sc];
    __shared__ float red[16];
    __shared__ float part[8][DHc];

    int tid = threadIdx.x, lane = tid & 31, warp = tid >> 5;

    float mx = -1e30f;
    for (int s = tid; s < Sc; s += 512) mx = fmaxf(mx, lg[s]);
#pragma unroll
    for (int o = 16; o; o >>= 1) mx = fmaxf(mx, __shfl_xor_sync(0xffffffffu, mx, o));
    if (lane == 0) red[warp] = mx;
    __syncthreads();
    mx = red[0];
#pragma unroll
    for (int i = 1; i < 16; i++) mx = fmaxf(mx, red[i]);
    __syncthreads();

    float sum = 0.f;
    for (int s = tid; s < Sc; s += 512) {
        float e = __expf(lg[s] - mx);
        sE[s] = e;
        sum += e;
    }
#pragma unroll
    for (int o = 16; o; o >>= 1) sum += __shfl_xor_sync(0xffffffffu, sum, o);
    if (lane == 0) red[warp] = sum;
    __syncthreads();
    float tot = 0.f;
#pragma unroll
    for (int i = 0; i < 16; i++) tot += red[i];
    float inv = 1.0f / tot;

    int j = tid & 63, gg = tid >> 6;
    const float* Xb = X + ((size_t)b * Sc) * Dc + h * DHc + j;
    float a0 = 0.f, a1 = 0.f, a2 = 0.f, a3 = 0.f;
    for (int s = gg; s < Sc; s += 32) {
        a0 += sE[s]      * Xb[(size_t)s * Dc];
        a1 += sE[s + 8]  * Xb[(size_t)(s + 8)  * Dc];
        a2 += sE[s + 16] * Xb[(size_t)(s + 16) * Dc];
        a3 += sE[s + 24] * Xb[(size_t)(s + 24) * Dc];
    }
    part[gg][j] = (a0 + a1) + (a2 + a3);
    __syncthreads();
    if (gg == 0) {
        float v = 0.f;
#pragma unroll
        for (int i = 0; i < 8; i++) v += part[i][j];
        v *= inv;
        if (qscale) v *= qscale[bh * DHc + j];
        out[bh * DHc + j] = v;
    }
}

// ===========================================================================
extern "C" void kernel_launch(void* const* d_in, const int* in_sizes, int n_in,
                              void* d_out, int out_size)
{
    const float* Qseq = (const float*)d_in[0];
    const float* Kseq = (const float*)d_in[1];
    const float* WQ = (const float*)d_in[3];
    const float* WK = (const float*)d_in[4];
    const float* Wa = (const float*)d_in[5];
    const float* Wb = (const float*)d_in[6];
    const float* WP = (const float*)d_in[7];
    float* out = (float*)d_out;

    float *pQ, *pK, *pQtf, *pWQ, *pWK, *pWP8, *pLA, *pLB, *pqg, *pkg;
    cudaGetSymbolAddress((void**)&pQ,   g_Q);
    cudaGetSymbolAddress((void**)&pK,   g_K);
    cudaGetSymbolAddress((void**)&pQtf, g_Qtf);
    cudaGetSymbolAddress((void**)&pWQ,  g_WQt);
    cudaGetSymbolAddress((void**)&pWK,  g_WKt);
    cudaGetSymbolAddress((void**)&pWP8, g_WP8);
    cudaGetSymbolAddress((void**)&pLA,  g_logA);
    cudaGetSymbolAddress((void**)&pLB,  g_logB);
    cudaGetSymbolAddress((void**)&pqg,  g_qg);
    cudaGetSymbolAddress((void**)&pkg,  g_kg);

    cudaFuncSetAttribute(gemm_mma<0>, cudaFuncAttributeMaxDynamicSharedMemorySize, GSMEM);
    cudaFuncSetAttribute(gemm_mma<1>, cudaFuncAttributeMaxDynamicSharedMemorySize, GSMEM);
    cudaFuncSetAttribute(gemm_mma<2>, cudaFuncAttributeMaxDynamicSharedMemorySize, GSMEM);

    dim3 tg(32, 32), tb(32, 8);
    dim3 gg(Dc / 128, Mc / 128);

    // launch order: gemm2 sits at profiled slot #4
    tcvt_k<<<tg, tb>>>(WQ, pWQ);                                     // 1
    tcvt_k<<<tg, tb>>>(WK, pWK);                                     // 2
    gemm_mma<1><<<gg, 128, GSMEM>>>(Qseq, pWQ, pQ, pQtf, nullptr);   // 3
    gemm_mma<0><<<gg, 128, GSMEM>>>(Kseq, pWK, pK, nullptr, nullptr);// 4 <- profiled

    logitsA_k<<<Mc / 8, 256>>>(Wa);
    pool_k<<<Bc * Hc, 512>>>(pLA, pQ, nullptr, pqg);
    logitsB_k<<<Mc / 8, 256>>>(Wb);
    pool_k<<<Bc * Hc, 512>>>(pLB, pK, pqg, pkg);

    dim3 wg(32, 32, 8);
    wp8t_k<<<wg, tb>>>(WP);
    gemm_mma<2><<<gg, 128, GSMEM>>>(pQtf, pWP8, out, nullptr, pQ);
}

// round 7
// speedup vs baseline: 1.2940x; 1.0221x over previous
#include <cuda_runtime.h>
#include <cstdint>

// ---------------------------------------------------------------------------
// Fastformer — tf32 mma.sync GEMMs, 64x64 warp tiles, 2-stage pipeline,
// 3 CTAs/SM for tensor-pipe occupancy.
// ---------------------------------------------------------------------------

#define Bc 8
#define Sc 2048
#define Dc 1024
#define Hc 16
#define DHc 64
#define Mc (Bc * Sc)   // 16384

__device__ float g_Q[Mc * Dc];
__device__ float g_K[Mc * Dc];
__device__ float g_Qtf[Mc * Dc];
__device__ float g_WQt[Dc * Dc];       // [n][k] transposed+tf32
__device__ float g_WKt[Dc * Dc];
__device__ float g_WP8[Bc * Dc * Dc];  // per-batch kg-scaled WP, [n][k]
__device__ float g_logA[Bc * Hc * Sc];
__device__ float g_logB[Bc * Hc * Sc];
__device__ float g_qg[Bc * Hc * DHc];
__device__ float g_kg[Bc * Dc];

// ===========================================================================
__device__ __forceinline__ uint32_t cvta_smem(const void* p) {
    uint32_t a;
    asm("{ .reg .u64 t; cvta.to.shared.u64 t, %1; cvt.u32.u64 %0, t; }" : "=r"(a) : "l"(p));
    return a;
}
__device__ __forceinline__ uint32_t f2tf(float x) {
    uint32_t u;
    asm("cvt.rna.tf32.f32 %0, %1;" : "=r"(u) : "f"(x));
    return u;
}
__device__ __forceinline__ float tff(float x) { return __uint_as_float(f2tf(x)); }

__device__ __forceinline__ void cp16(uint32_t s, const void* g) {
    asm volatile("cp.async.cg.shared.global [%0], [%1], 16;" :: "r"(s), "l"(g));
}
__device__ __forceinline__ void cp_commit() {
    asm volatile("cp.async.commit_group;" ::: "memory");
}
template <int N>
__device__ __forceinline__ void cp_wait() {
    asm volatile("cp.async.wait_group %0;" :: "n"(N) : "memory");
}
__device__ __forceinline__ void ldmx4(uint32_t& r0, uint32_t& r1, uint32_t& r2, uint32_t& r3,
                                      uint32_t addr) {
    asm volatile("ldmatrix.sync.aligned.m8n8.x4.shared.b16 {%0,%1,%2,%3}, [%4];"
                 : "=r"(r0), "=r"(r1), "=r"(r2), "=r"(r3) : "r"(addr));
}
__device__ __forceinline__ void mma_tf32(float& c0, float& c1, float& c2, float& c3,
                                         uint32_t a0, uint32_t a1, uint32_t a2, uint32_t a3,
                                         uint32_t b0, uint32_t b1) {
    asm volatile(
        "mma.sync.aligned.m16n8k8.row.col.f32.tf32.tf32.f32 "
        "{%0,%1,%2,%3}, {%4,%5,%6,%7}, {%8,%9}, {%0,%1,%2,%3};"
        : "+f"(c0), "+f"(c1), "+f"(c2), "+f"(c3)
        : "r"(a0), "r"(a1), "r"(a2), "r"(a3), "r"(b0), "r"(b1));
}

// ===========================================================================
// GEMM: C[M,N] = A[M,K] @ Bt[N,K]^T.  BM=BN=128, BK=32, 128 thr (2x2 warps,
// 64x64 tiles), 2-stage cp.async, ldmatrix.x4, 3 CTAs/SM.
// MODE 0: A raw fp32 (cvt in-reg), store C.
// MODE 1: like 0, plus Ctf (tf32-rounded copy of C).
// MODE 2: A pre-rounded, Bt per-batch, epilogue += resid.
// ===========================================================================
#define TILEB (128 * 144)           // bytes per matrix tile (row stride 144B)
#define STGB (2 * TILEB)            // 36864
#define NSTAGE 2
#define GSMEM (NSTAGE * STGB)       // 73728
#define NCH (Dc / 32)               // 32

template <int MODE>
__global__ __launch_bounds__(128, 3)
void gemm_mma(const float* __restrict__ A, const float* __restrict__ Bt,
              float* __restrict__ C, float* __restrict__ Ctf,
              const float* __restrict__ resid)
{
    constexpr bool CVTA = (MODE != 2);
    extern __shared__ char smem[];
    const uint32_t sb = cvta_smem(smem);
    const int tid  = threadIdx.x;
    const int wid  = tid >> 5, lane = tid & 31;
    const int g    = lane >> 2, t = lane & 3;
    const int wm   = wid >> 1, wn = wid & 1;
    const int crow = blockIdx.y * 128, ccol = blockIdx.x * 128;

    if (MODE == 2) Bt += (size_t)(crow / Sc) * Dc * Dc;

    // loaders: 8 threads/row (16B each); 16 rows per pass, 8 passes
    const int lrow = tid >> 3, seg = tid & 7;
    const float* Ag = A  + (size_t)(crow + lrow) * Dc + seg * 4;
    const float* Bg = Bt + (size_t)(ccol + lrow) * Dc + seg * 4;
    const uint32_t sA = (uint32_t)(lrow * 144 + seg * 16);
    const uint32_t sB = (uint32_t)(TILEB + lrow * 144 + seg * 16);

    // ldmatrix per-lane offsets
    const int ltile = lane >> 3, lr = lane & 7;
    uint32_t offA[4], offB[4];
#pragma unroll
    for (int im = 0; im < 4; im++)
        offA[im] = (uint32_t)((wm * 64 + im * 16 + (ltile & 1) * 8 + lr) * 144 + (ltile >> 1) * 16);
#pragma unroll
    for (int j = 0; j < 4; j++)
        offB[j] = (uint32_t)(TILEB + (wn * 64 + j * 16 + (ltile & 1) * 8 + lr) * 144 + (ltile >> 1) * 16);

    float acc[4][8][4];
#pragma unroll
    for (int i = 0; i < 4; i++)
#pragma unroll
        for (int j = 0; j < 8; j++)
#pragma unroll
            for (int k = 0; k < 4; k++) acc[i][j][k] = 0.f;

    auto issue = [&](int c) {
        uint32_t base = sb + (uint32_t)(c & 1) * STGB;
        const float* ag = Ag + c * 32;
        const float* bg = Bg + c * 32;
#pragma unroll
        for (int rr = 0; rr < 8; rr++) {
            cp16(base + sA + rr * (16 * 144), ag + (size_t)rr * 16 * Dc);
            cp16(base + sB + rr * (16 * 144), bg + (size_t)rr * 16 * Dc);
        }
        cp_commit();
    };

    issue(0);

    for (int c = 0; c < NCH; c++) {
        cp_wait<0>();
        __syncthreads();
        if (c + 1 < NCH) issue(c + 1);   // writes slot (c+1)&1, we read slot c&1

        const uint32_t base = sb + (uint32_t)(c & 1) * STGB;

#pragma unroll
        for (int kk = 0; kk < 4; kk++) {
            uint32_t a[4][4], b[8][2];
#pragma unroll
            for (int im = 0; im < 4; im++)
                ldmx4(a[im][0], a[im][1], a[im][2], a[im][3], base + offA[im] + kk * 32);
#pragma unroll
            for (int j = 0; j < 4; j++) {
                uint32_t r0, r1, r2, r3;
                ldmx4(r0, r1, r2, r3, base + offB[j] + kk * 32);
                b[2 * j][0] = r0; b[2 * j + 1][0] = r1;
                b[2 * j][1] = r2; b[2 * j + 1][1] = r3;
            }
            if (CVTA) {
#pragma unroll
                for (int im = 0; im < 4; im++)
#pragma unroll
                    for (int r = 0; r < 4; r++)
                        a[im][r] = f2tf(__uint_as_float(a[im][r]));
            }
#pragma unroll
            for (int im = 0; im < 4; im++)
#pragma unroll
                for (int in = 0; in < 8; in++)
                    mma_tf32(acc[im][in][0], acc[im][in][1], acc[im][in][2], acc[im][in][3],
                             a[im][0], a[im][1], a[im][2], a[im][3],
                             b[in][0], b[in][1]);
        }
        __syncthreads();   // all warps done with slot c before its reuse at c+2
    }

    // epilogue (fragment rows g, g+8; cols 2t, 2t+1)
#pragma unroll
    for (int im = 0; im < 4; im++) {
#pragma unroll
        for (int in = 0; in < 8; in++) {
            const int r0 = crow + wm * 64 + im * 16 + g;
            const int cc = ccol + wn * 64 + in * 8 + 2 * t;
            float2 v0 = make_float2(acc[im][in][0], acc[im][in][1]);
            float2 v1 = make_float2(acc[im][in][2], acc[im][in][3]);
            if (MODE == 2) {
                float2 q0 = *(const float2*)(resid + (size_t)r0 * Dc + cc);
                float2 q1 = *(const float2*)(resid + (size_t)(r0 + 8) * Dc + cc);
                v0.x += q0.x; v0.y += q0.y; v1.x += q1.x; v1.y += q1.y;
            }
            *(float2*)(C + (size_t)r0 * Dc + cc) = v0;
            *(float2*)(C + (size_t)(r0 + 8) * Dc + cc) = v1;
            if (MODE == 1) {
                *(float2*)(Ctf + (size_t)r0 * Dc + cc) = make_float2(tff(v0.x), tff(v0.y));
                *(float2*)(Ctf + (size_t)(r0 + 8) * Dc + cc) = make_float2(tff(v1.x), tff(v1.y));
            }
        }
    }
}

// ===========================================================================
__global__ void tcvt_k(const float* __restrict__ W, float* __restrict__ Wt)
{
    __shared__ float tbuf[32][33];
    int n0 = blockIdx.x * 32, k0 = blockIdx.y * 32;
    int tx = threadIdx.x, ty = threadIdx.y;
#pragma unroll
    for (int i = 0; i < 32; i += 8) tbuf[ty + i][tx] = W[(size_t)(k0 + ty + i) * Dc + n0 + tx];
    __syncthreads();
#pragma unroll
    for (int i = 0; i < 32; i += 8)
        Wt[(size_t)(n0 + ty + i) * Dc + k0 + tx] = tff(tbuf[tx][ty + i]);
}

__global__ void wp8t_k(const float* __restrict__ WP)
{
    __shared__ float tbuf[32][33];
    int n0 = blockIdx.x * 32, k0 = blockIdx.y * 32, b = blockIdx.z;
    int tx = threadIdx.x, ty = threadIdx.y;
#pragma unroll
    for (int i = 0; i < 32; i += 8)
        tbuf[ty + i][tx] = WP[(size_t)(k0 + ty + i) * Dc + n0 + tx] * g_kg[b * Dc + k0 + ty + i];
    __syncthreads();
    float* outb = g_WP8 + (size_t)b * Dc * Dc;
#pragma unroll
    for (int i = 0; i < 32; i += 8)
        outb[(size_t)(n0 + ty + i) * Dc + k0 + tx] = tff(tbuf[tx][ty + i]);
}

// ===========================================================================
__global__ void logitsA_k(const float* __restrict__ Wa)
{
    int gw = (blockIdx.x * blockDim.x + threadIdx.x) >> 5;
    if (gw >= Mc) return;
    int lane = threadIdx.x & 31;
    int b = gw >> 11, s = gw & 2047;

    const float* q = g_Q + (size_t)gw * Dc;
    float acc[16];
#pragma unroll
    for (int e = 0; e < 16; e++) acc[e] = 0.f;

    for (int d = lane; d < Dc; d += 32) {
        float qv = q[d];
        const float4* w4 = reinterpret_cast<const float4*>(Wa + d * 16);
        float4 w0 = w4[0], w1 = w4[1], w2 = w4[2], w3 = w4[3];
        acc[0]  += qv * w0.x; acc[1]  += qv * w0.y; acc[2]  += qv * w0.z; acc[3]  += qv * w0.w;
        acc[4]  += qv * w1.x; acc[5]  += qv * w1.y; acc[6]  += qv * w1.z; acc[7]  += qv * w1.w;
        acc[8]  += qv * w2.x; acc[9]  += qv * w2.y; acc[10] += qv * w2.z; acc[11] += qv * w2.w;
        acc[12] += qv * w3.x; acc[13] += qv * w3.y; acc[14] += qv * w3.z; acc[15] += qv * w3.w;
    }
#pragma unroll
    for (int e = 0; e < 16; e++) {
        float v = acc[e];
#pragma unroll
        for (int o = 16; o; o >>= 1) v += __shfl_xor_sync(0xffffffffu, v, o);
        if (lane == e) g_logA[(b * Hc + e) * Sc + s] = v * 0.125f;
    }
}

__global__ void logitsB_k(const float* __restrict__ Wb)
{
    int gw = (blockIdx.x * blockDim.x + threadIdx.x) >> 5;
    if (gw >= Mc) return;
    int lane = threadIdx.x & 31;
    int b = gw >> 11, sp = gw & 2047;
    int h0 = sp >> 7, s0 = (sp & 127) << 4;

    const float* qgv = g_qg + (b * Hc + h0) * DHc;
    const float* Kb  = g_K + ((size_t)(b * Sc + s0)) * Dc + h0 * DHc;

    float acc[16];
#pragma unroll
    for (int e = 0; e < 16; e++) acc[e] = 0.f;

    for (int k = lane; k < Dc; k += 32) {
        int tt = k >> 6, j = k & 63;
        float v = Kb[(size_t)tt * Dc + j] * qgv[j];
        const float4* w4 = reinterpret_cast<const float4*>(Wb + k * 16);
        float4 w0 = w4[0], w1 = w4[1], w2 = w4[2], w3 = w4[3];
        acc[0]  += v * w0.x; acc[1]  += v * w0.y; acc[2]  += v * w0.z; acc[3]  += v * w0.w;
        acc[4]  += v * w1.x; acc[5]  += v * w1.y; acc[6]  += v * w1.z; acc[7]  += v * w1.w;
        acc[8]  += v * w2.x; acc[9]  += v * w2.y; acc[10] += v * w2.z; acc[11] += v * w2.w;
        acc[12] += v * w3.x; acc[13] += v * w3.y; acc[14] += v * w3.z; acc[15] += v * w3.w;
    }
#pragma unroll
    for (int e = 0; e < 16; e++) {
        float v = acc[e];
#pragma unroll
        for (int o = 16; o; o >>= 1) v += __shfl_xor_sync(0xffffffffu, v, o);
        if (lane == e) g_logB[(b * Hc + e) * Sc + sp] = v * 0.125f;
    }
}

// ===========================================================================
__global__ void pool_k(const float* __restrict__ logits, const float* __restrict__ X,
                       const float* __restrict__ qscale, float* __restrict__ out)
{
    int bh = blockIdx.x;
    int b = bh >> 4, h = bh & 15;
    const float* lg = logits + bh * Sc;

    __shared__ float sE[Sc];
    __shared__ float red[16];
    __shared__ float part[8][DHc];

    int tid = threadIdx.x, lane = tid & 31, warp = tid >> 5;

    float mx = -1e30f;
    for (int s = tid; s < Sc; s += 512) mx = fmaxf(mx, lg[s]);
#pragma unroll
    for (int o = 16; o; o >>= 1) mx = fmaxf(mx, __shfl_xor_sync(0xffffffffu, mx, o));
    if (lane == 0) red[warp] = mx;
    __syncthreads();
    mx = red[0];
#pragma unroll
    for (int i = 1; i < 16; i++) mx = fmaxf(mx, red[i]);
    __syncthreads();

    float sum = 0.f;
    for (int s = tid; s < Sc; s += 512) {
        float e = __expf(lg[s] - mx);
        sE[s] = e;
        sum += e;
    }
#pragma unroll
    for (int o = 16; o; o >>= 1) sum += __shfl_xor_sync(0xffffffffu, sum, o);
    if (lane == 0) red[warp] = sum;
    __syncthreads();
    float tot = 0.f;
#pragma unroll
    for (int i = 0; i < 16; i++) tot += red[i];
    float inv = 1.0f / tot;

    int j = tid & 63, gg = tid >> 6;
    const float* Xb = X + ((size_t)b * Sc) * Dc + h * DHc + j;
    float a0 = 0.f, a1 = 0.f, a2 = 0.f, a3 = 0.f;
    for (int s = gg; s < Sc; s += 32) {
        a0 += sE[s]      * Xb[(size_t)s * Dc];
        a1 += sE[s + 8]  * Xb[(size_t)(s + 8)  * Dc];
        a2 += sE[s + 16] * Xb[(size_t)(s + 16) * Dc];
        a3 += sE[s + 24] * Xb[(size_t)(s + 24) * Dc];
    }
    part[gg][j] = (a0 + a1) + (a2 + a3);
    __syncthreads();
    if (gg == 0) {
        float v = 0.f;
#pragma unroll
        for (int i = 0; i < 8; i++) v += part[i][j];
        v *= inv;
        if (qscale) v *= qscale[bh * DHc + j];
        out[bh * DHc + j] = v;
    }
}

// ===========================================================================
extern "C" void kernel_launch(void* const* d_in, const int* in_sizes, int n_in,
                              void* d_out, int out_size)
{
    const float* Qseq = (const float*)d_in[0];
    const float* Kseq = (const float*)d_in[1];
    const float* WQ = (const float*)d_in[3];
    const float* WK = (const float*)d_in[4];
    const float* Wa = (const float*)d_in[5];
    const float* Wb = (const float*)d_in[6];
    const float* WP = (const float*)d_in[7];
    float* out = (float*)d_out;

    float *pQ, *pK, *pQtf, *pWQ, *pWK, *pWP8, *pLA, *pLB, *pqg, *pkg;
    cudaGetSymbolAddress((void**)&pQ,   g_Q);
    cudaGetSymbolAddress((void**)&pK,   g_K);
    cudaGetSymbolAddress((void**)&pQtf, g_Qtf);
    cudaGetSymbolAddress((void**)&pWQ,  g_WQt);
    cudaGetSymbolAddress((void**)&pWK,  g_WKt);
    cudaGetSymbolAddress((void**)&pWP8, g_WP8);
    cudaGetSymbolAddress((void**)&pLA,  g_logA);
    cudaGetSymbolAddress((void**)&pLB,  g_logB);
    cudaGetSymbolAddress((void**)&pqg,  g_qg);
    cudaGetSymbolAddress((void**)&pkg,  g_kg);

    cudaFuncSetAttribute(gemm_mma<0>, cudaFuncAttributeMaxDynamicSharedMemorySize, GSMEM);
    cudaFuncSetAttribute(gemm_mma<1>, cudaFuncAttributeMaxDynamicSharedMemorySize, GSMEM);
    cudaFuncSetAttribute(gemm_mma<2>, cudaFuncAttributeMaxDynamicSharedMemorySize, GSMEM);

    dim3 tg(32, 32), tb(32, 8);
    dim3 gg(Dc / 128, Mc / 128);

    // launch order: gemm2 sits at profiled slot #4
    tcvt_k<<<tg, tb>>>(WQ, pWQ);                                     // 1
    tcvt_k<<<tg, tb>>>(WK, pWK);                                     // 2
    gemm_mma<1><<<gg, 128, GSMEM>>>(Qseq, pWQ, pQ, pQtf, nullptr);   // 3
    gemm_mma<0><<<gg, 128, GSMEM>>>(Kseq, pWK, pK, nullptr, nullptr);// 4 <- profiled

    logitsA_k<<<Mc / 8, 256>>>(Wa);
    pool_k<<<Bc * Hc, 512>>>(pLA, pQ, nullptr, pqg);
    logitsB_k<<<Mc / 8, 256>>>(Wb);
    pool_k<<<Bc * Hc, 512>>>(pLB, pK, pqg, pkg);

    dim3 wg(32, 32, 8);
    wp8t_k<<<wg, tb>>>(WP);
    gemm_mma<2><<<gg, 128, GSMEM>>>(pQtf, pWP8, out, nullptr, pQ);
}

// round 8
// speedup vs baseline: 1.4344x; 1.1086x over previous
#include <cuda_runtime.h>
#include <cstdint>

// ---------------------------------------------------------------------------
// Fastformer — tf32 mma.sync GEMMs (64x64 warp tiles, 2-stage, 3 CTA/SM),
// kg-scale fused into GEMM3 A-fragments, 4-row logits kernels.
// ---------------------------------------------------------------------------

#define Bc 8
#define Sc 2048
#define Dc 1024
#define Hc 16
#define DHc 64
#define Mc (Bc * Sc)   // 16384

__device__ float g_Q[Mc * Dc];
__device__ float g_K[Mc * Dc];
__device__ float g_WQt[Dc * Dc];       // [n][k] transposed+tf32
__device__ float g_WKt[Dc * Dc];
__device__ float g_WPt[Dc * Dc];
__device__ float g_logA[Bc * Hc * Sc];
__device__ float g_logB[Bc * Hc * Sc];
__device__ float g_qg[Bc * Hc * DHc];
__device__ float g_kg[Bc * Dc];

// ===========================================================================
__device__ __forceinline__ uint32_t cvta_smem(const void* p) {
    uint32_t a;
    asm("{ .reg .u64 t; cvta.to.shared.u64 t, %1; cvt.u32.u64 %0, t; }" : "=r"(a) : "l"(p));
    return a;
}
__device__ __forceinline__ uint32_t f2tf(float x) {
    uint32_t u;
    asm("cvt.rna.tf32.f32 %0, %1;" : "=r"(u) : "f"(x));
    return u;
}
__device__ __forceinline__ float tff(float x) { return __uint_as_float(f2tf(x)); }

__device__ __forceinline__ void cp16(uint32_t s, const void* g) {
    asm volatile("cp.async.cg.shared.global [%0], [%1], 16;" :: "r"(s), "l"(g));
}
__device__ __forceinline__ void cp_commit() {
    asm volatile("cp.async.commit_group;" ::: "memory");
}
template <int N>
__device__ __forceinline__ void cp_wait() {
    asm volatile("cp.async.wait_group %0;" :: "n"(N) : "memory");
}
__device__ __forceinline__ void ldmx4(uint32_t& r0, uint32_t& r1, uint32_t& r2, uint32_t& r3,
                                      uint32_t addr) {
    asm volatile("ldmatrix.sync.aligned.m8n8.x4.shared.b16 {%0,%1,%2,%3}, [%4];"
                 : "=r"(r0), "=r"(r1), "=r"(r2), "=r"(r3) : "r"(addr));
}
__device__ __forceinline__ void mma_tf32(float& c0, float& c1, float& c2, float& c3,
                                         uint32_t a0, uint32_t a1, uint32_t a2, uint32_t a3,
                                         uint32_t b0, uint32_t b1) {
    asm volatile(
        "mma.sync.aligned.m16n8k8.row.col.f32.tf32.tf32.f32 "
        "{%0,%1,%2,%3}, {%4,%5,%6,%7}, {%8,%9}, {%0,%1,%2,%3};"
        : "+f"(c0), "+f"(c1), "+f"(c2), "+f"(c3)
        : "r"(a0), "r"(a1), "r"(a2), "r"(a3), "r"(b0), "r"(b1));
}

// ===========================================================================
// GEMM: C[M,N] = A[M,K] @ Bt[N,K]^T.  BM=BN=128, BK=32, 128 thr (2x2 warps,
// 64x64 tiles), 2-stage cp.async, ldmatrix.x4, 3 CTAs/SM. A raw fp32.
// MODE 0: cvt A in-reg, store C.
// MODE 2: scale A in-reg by Kg[b, k] then cvt; epilogue += resid.
//   (A-frag k mapping: a0/a1 at k = kbase+kk*8+t, a2/a3 at +4.)
// ===========================================================================
#define TILEB (128 * 144)           // bytes per matrix tile (row stride 144B)
#define STGB (2 * TILEB)            // 36864
#define GSMEM (2 * STGB)            // 73728
#define NCH (Dc / 32)               // 32

template <int MODE>
__global__ __launch_bounds__(128, 3)
void gemm_mma(const float* __restrict__ A, const float* __restrict__ Bt,
              float* __restrict__ C, const float* __restrict__ resid,
              const float* __restrict__ Kg)
{
    extern __shared__ char smem[];
    const uint32_t sb = cvta_smem(smem);
    const int tid  = threadIdx.x;
    const int wid  = tid >> 5, lane = tid & 31;
    const int g    = lane >> 2, t = lane & 3;
    const int wm   = wid >> 1, wn = wid & 1;
    const int crow = blockIdx.y * 128, ccol = blockIdx.x * 128;

    const float* kgp = (MODE == 2) ? (Kg + (size_t)(crow / Sc) * Dc) : nullptr;

    // loaders: 8 threads/row (16B each); 16 rows per pass, 8 passes
    const int lrow = tid >> 3, seg = tid & 7;
    const float* Ag = A  + (size_t)(crow + lrow) * Dc + seg * 4;
    const float* Bg = Bt + (size_t)(ccol + lrow) * Dc + seg * 4;
    const uint32_t sA = (uint32_t)(lrow * 144 + seg * 16);
    const uint32_t sB = (uint32_t)(TILEB + lrow * 144 + seg * 16);

    // ldmatrix per-lane offsets
    const int ltile = lane >> 3, lr = lane & 7;
    uint32_t offA[4], offB[4];
#pragma unroll
    for (int im = 0; im < 4; im++)
        offA[im] = (uint32_t)((wm * 64 + im * 16 + (ltile & 1) * 8 + lr) * 144 + (ltile >> 1) * 16);
#pragma unroll
    for (int j = 0; j < 4; j++)
        offB[j] = (uint32_t)(TILEB + (wn * 64 + j * 16 + (ltile & 1) * 8 + lr) * 144 + (ltile >> 1) * 16);

    float acc[4][8][4];
#pragma unroll
    for (int i = 0; i < 4; i++)
#pragma unroll
        for (int j = 0; j < 8; j++)
#pragma unroll
            for (int k = 0; k < 4; k++) acc[i][j][k] = 0.f;

    auto issue = [&](int c) {
        uint32_t base = sb + (uint32_t)(c & 1) * STGB;
        const float* ag = Ag + c * 32;
        const float* bg = Bg + c * 32;
#pragma unroll
        for (int rr = 0; rr < 8; rr++) {
            cp16(base + sA + rr * (16 * 144), ag + (size_t)rr * 16 * Dc);
            cp16(base + sB + rr * (16 * 144), bg + (size_t)rr * 16 * Dc);
        }
        cp_commit();
    };

    issue(0);

    for (int c = 0; c < NCH; c++) {
        cp_wait<0>();
        __syncthreads();
        if (c + 1 < NCH) issue(c + 1);

        const uint32_t base = sb + (uint32_t)(c & 1) * STGB;

        float kgs[8];
        if (MODE == 2) {
#pragma unroll
            for (int j = 0; j < 8; j++) kgs[j] = kgp[c * 32 + t + 4 * j];
        }

#pragma unroll
        for (int kk = 0; kk < 4; kk++) {
            uint32_t a[4][4], b[8][2];
#pragma unroll
            for (int im = 0; im < 4; im++)
                ldmx4(a[im][0], a[im][1], a[im][2], a[im][3], base + offA[im] + kk * 32);
#pragma unroll
            for (int j = 0; j < 4; j++) {
                uint32_t r0, r1, r2, r3;
                ldmx4(r0, r1, r2, r3, base + offB[j] + kk * 32);
                b[2 * j][0] = r0; b[2 * j + 1][0] = r1;
                b[2 * j][1] = r2; b[2 * j + 1][1] = r3;
            }
            if (MODE == 2) {
                const float s0 = kgs[2 * kk], s1 = kgs[2 * kk + 1];
#pragma unroll
                for (int im = 0; im < 4; im++) {
                    a[im][0] = f2tf(__uint_as_float(a[im][0]) * s0);
                    a[im][1] = f2tf(__uint_as_float(a[im][1]) * s0);
                    a[im][2] = f2tf(__uint_as_float(a[im][2]) * s1);
                    a[im][3] = f2tf(__uint_as_float(a[im][3]) * s1);
                }
            } else {
#pragma unroll
                for (int im = 0; im < 4; im++)
#pragma unroll
                    for (int r = 0; r < 4; r++)
                        a[im][r] = f2tf(__uint_as_float(a[im][r]));
            }
#pragma unroll
            for (int im = 0; im < 4; im++)
#pragma unroll
                for (int in = 0; in < 8; in++)
                    mma_tf32(acc[im][in][0], acc[im][in][1], acc[im][in][2], acc[im][in][3],
                             a[im][0], a[im][1], a[im][2], a[im][3],
                             b[in][0], b[in][1]);
        }
        __syncthreads();
    }

    // epilogue (fragment rows g, g+8; cols 2t, 2t+1)
#pragma unroll
    for (int im = 0; im < 4; im++) {
#pragma unroll
        for (int in = 0; in < 8; in++) {
            const int r0 = crow + wm * 64 + im * 16 + g;
            const int cc = ccol + wn * 64 + in * 8 + 2 * t;
            float2 v0 = make_float2(acc[im][in][0], acc[im][in][1]);
            float2 v1 = make_float2(acc[im][in][2], acc[im][in][3]);
            if (MODE == 2) {
                float2 q0 = *(const float2*)(resid + (size_t)r0 * Dc + cc);
                float2 q1 = *(const float2*)(resid + (size_t)(r0 + 8) * Dc + cc);
                v0.x += q0.x; v0.y += q0.y; v1.x += q1.x; v1.y += q1.y;
            }
            *(float2*)(C + (size_t)r0 * Dc + cc) = v0;
            *(float2*)(C + (size_t)(r0 + 8) * Dc + cc) = v1;
        }
    }
}

// ===========================================================================
__global__ void tcvt_k(const float* __restrict__ W, float* __restrict__ Wt)
{
    __shared__ float tbuf[32][33];
    int n0 = blockIdx.x * 32, k0 = blockIdx.y * 32;
    int tx = threadIdx.x, ty = threadIdx.y;
#pragma unroll
    for (int i = 0; i < 32; i += 8) tbuf[ty + i][tx] = W[(size_t)(k0 + ty + i) * Dc + n0 + tx];
    __syncthreads();
#pragma unroll
    for (int i = 0; i < 32; i += 8)
        Wt[(size_t)(n0 + ty + i) * Dc + k0 + tx] = tff(tbuf[tx][ty + i]);
}

// ===========================================================================
// logitsA: one warp per 4 rows. logA[b,e,s] = 0.125 * sum_d Q[b,s,d]*Wa[d,e]
// ===========================================================================
__global__ void logitsA_k(const float* __restrict__ Wa)
{
    int gw = (blockIdx.x * blockDim.x + threadIdx.x) >> 5;   // 0..4095
    int lane = threadIdx.x & 31;
    int b = gw >> 9;
    int s0 = (gw << 2) & 2047;
    const float* q = g_Q + ((size_t)gw << 2) * Dc;

    float acc[4][16];
#pragma unroll
    for (int r = 0; r < 4; r++)
#pragma unroll
        for (int e = 0; e < 16; e++) acc[r][e] = 0.f;

    for (int i = 0; i < 8; i++) {
        int d4 = lane + 32 * i;                       // float4 index; d = 4*d4
        float4 qv[4];
#pragma unroll
        for (int r = 0; r < 4; r++)
            qv[r] = reinterpret_cast<const float4*>(q + (size_t)r * Dc)[d4];
        const float4* wa = reinterpret_cast<const float4*>(Wa) + (size_t)d4 * 16;
#pragma unroll
        for (int dd = 0; dd < 4; dd++) {
            float4 w0 = wa[dd * 4 + 0], w1 = wa[dd * 4 + 1];
            float4 w2 = wa[dd * 4 + 2], w3 = wa[dd * 4 + 3];
            float qs[4];
            qs[0] = (dd == 0) ? qv[0].x : (dd == 1) ? qv[0].y : (dd == 2) ? qv[0].z : qv[0].w;
            qs[1] = (dd == 0) ? qv[1].x : (dd == 1) ? qv[1].y : (dd == 2) ? qv[1].z : qv[1].w;
            qs[2] = (dd == 0) ? qv[2].x : (dd == 1) ? qv[2].y : (dd == 2) ? qv[2].z : qv[2].w;
            qs[3] = (dd == 0) ? qv[3].x : (dd == 1) ? qv[3].y : (dd == 2) ? qv[3].z : qv[3].w;
#pragma unroll
            for (int r = 0; r < 4; r++) {
                acc[r][0]  += qs[r] * w0.x; acc[r][1]  += qs[r] * w0.y;
                acc[r][2]  += qs[r] * w0.z; acc[r][3]  += qs[r] * w0.w;
                acc[r][4]  += qs[r] * w1.x; acc[r][5]  += qs[r] * w1.y;
                acc[r][6]  += qs[r] * w1.z; acc[r][7]  += qs[r] * w1.w;
                acc[r][8]  += qs[r] * w2.x; acc[r][9]  += qs[r] * w2.y;
                acc[r][10] += qs[r] * w2.z; acc[r][11] += qs[r] * w2.w;
                acc[r][12] += qs[r] * w3.x; acc[r][13] += qs[r] * w3.y;
                acc[r][14] += qs[r] * w3.z; acc[r][15] += qs[r] * w3.w;
            }
        }
    }

#pragma unroll
    for (int e = 0; e < 16; e++) {
        float v0 = acc[0][e], v1 = acc[1][e], v2 = acc[2][e], v3 = acc[3][e];
#pragma unroll
        for (int o = 16; o; o >>= 1) {
            v0 += __shfl_xor_sync(0xffffffffu, v0, o);
            v1 += __shfl_xor_sync(0xffffffffu, v1, o);
            v2 += __shfl_xor_sync(0xffffffffu, v2, o);
            v3 += __shfl_xor_sync(0xffffffffu, v3, o);
        }
        if (lane == e) {
            float* dst = g_logA + (b * Hc + e) * Sc + s0;
            dst[0] = v0 * 0.125f; dst[1] = v1 * 0.125f;
            dst[2] = v2 * 0.125f; dst[3] = v3 * 0.125f;
        }
    }
}

// ===========================================================================
// logitsB: one warp per 4 scrambled rows (same h0 by alignment).
//   h0 = spL/128, s0 = (spL%128)*16; row i uses s0 + 16*i.
// ===========================================================================
__global__ void logitsB_k(const float* __restrict__ Wb)
{
    int gw = (blockIdx.x * blockDim.x + threadIdx.x) >> 5;   // 0..4095
    int lane = threadIdx.x & 31;
    int b = gw >> 9;
    int spL = (gw << 2) & 2047;
    int h0 = spL >> 7;
    int s0 = (spL & 127) << 4;

    const float* qgv = g_qg + (b * Hc + h0) * DHc;
    const float* Kb  = g_K + ((size_t)(b * Sc + s0)) * Dc + h0 * DHc;

    float acc[4][16];
#pragma unroll
    for (int r = 0; r < 4; r++)
#pragma unroll
        for (int e = 0; e < 16; e++) acc[r][e] = 0.f;

    for (int i = 0; i < 32; i++) {
        int k = lane + 32 * i;
        int tt = k >> 6, j = k & 63;
        float qv = qgv[j];
        float vr[4];
#pragma unroll
        for (int r = 0; r < 4; r++)
            vr[r] = Kb[(size_t)(r * 16 + tt) * Dc + j] * qv;
        const float4* w4 = reinterpret_cast<const float4*>(Wb + k * 16);
        float4 w0 = w4[0], w1 = w4[1], w2 = w4[2], w3 = w4[3];
#pragma unroll
        for (int r = 0; r < 4; r++) {
            acc[r][0]  += vr[r] * w0.x; acc[r][1]  += vr[r] * w0.y;
            acc[r][2]  += vr[r] * w0.z; acc[r][3]  += vr[r] * w0.w;
            acc[r][4]  += vr[r] * w1.x; acc[r][5]  += vr[r] * w1.y;
            acc[r][6]  += vr[r] * w1.z; acc[r][7]  += vr[r] * w1.w;
            acc[r][8]  += vr[r] * w2.x; acc[r][9]  += vr[r] * w2.y;
            acc[r][10] += vr[r] * w2.z; acc[r][11] += vr[r] * w2.w;
            acc[r][12] += vr[r] * w3.x; acc[r][13] += vr[r] * w3.y;
            acc[r][14] += vr[r] * w3.z; acc[r][15] += vr[r] * w3.w;
        }
    }

#pragma unroll
    for (int e = 0; e < 16; e++) {
        float v0 = acc[0][e], v1 = acc[1][e], v2 = acc[2][e], v3 = acc[3][e];
#pragma unroll
        for (int o = 16; o; o >>= 1) {
            v0 += __shfl_xor_sync(0xffffffffu, v0, o);
            v1 += __shfl_xor_sync(0xffffffffu, v1, o);
            v2 += __shfl_xor_sync(0xffffffffu, v2, o);
            v3 += __shfl_xor_sync(0xffffffffu, v3, o);
        }
        if (lane == e) {
            float* dst = g_logB + (b * Hc + e) * Sc + spL;
            dst[0] = v0 * 0.125f; dst[1] = v1 * 0.125f;
            dst[2] = v2 * 0.125f; dst[3] = v3 * 0.125f;
        }
    }
}

// ===========================================================================
__global__ void pool_k(const float* __restrict__ logits, const float* __restrict__ X,
                       const float* __restrict__ qscale, float* __restrict__ out)
{
    int bh = blockIdx.x;
    int b = bh >> 4, h = bh & 15;
    const float* lg = logits + bh * Sc;

    __shared__ float sE[Sc];
    __shared__ float red[16];
    __shared__ float part[8][DHc];

    int tid = threadIdx.x, lane = tid & 31, warp = tid >> 5;

    float mx = -1e30f;
    for (int s = tid; s < Sc; s += 512) mx = fmaxf(mx, lg[s]);
#pragma unroll
    for (int o = 16; o; o >>= 1) mx = fmaxf(mx, __shfl_xor_sync(0xffffffffu, mx, o));
    if (lane == 0) red[warp] = mx;
    __syncthreads();
    mx = red[0];
#pragma unroll
    for (int i = 1; i < 16; i++) mx = fmaxf(mx, red[i]);
    __syncthreads();

    float sum = 0.f;
    for (int s = tid; s < Sc; s += 512) {
        float e = __expf(lg[s] - mx);
        sE[s] = e;
        sum += e;
    }
#pragma unroll
    for (int o = 16; o; o >>= 1) sum += __shfl_xor_sync(0xffffffffu, sum, o);
    if (lane == 0) red[warp] = sum;
    __syncthreads();
    float tot = 0.f;
#pragma unroll
    for (int i = 0; i < 16; i++) tot += red[i];
    float inv = 1.0f / tot;

    int j = tid & 63, gg = tid >> 6;
    const float* Xb = X + ((size_t)b * Sc) * Dc + h * DHc + j;
    float a0 = 0.f, a1 = 0.f, a2 = 0.f, a3 = 0.f;
    for (int s = gg; s < Sc; s += 32) {
        a0 += sE[s]      * Xb[(size_t)s * Dc];
        a1 += sE[s + 8]  * Xb[(size_t)(s + 8)  * Dc];
        a2 += sE[s + 16] * Xb[(size_t)(s + 16) * Dc];
        a3 += sE[s + 24] * Xb[(size_t)(s + 24) * Dc];
    }
    part[gg][j] = (a0 + a1) + (a2 + a3);
    __syncthreads();
    if (gg == 0) {
        float v = 0.f;
#pragma unroll
        for (int i = 0; i < 8; i++) v += part[i][j];
        v *= inv;
        if (qscale) v *= qscale[bh * DHc + j];
        out[bh * DHc + j] = v;
    }
}

// ===========================================================================
extern "C" void kernel_launch(void* const* d_in, const int* in_sizes, int n_in,
                              void* d_out, int out_size)
{
    const float* Qseq = (const float*)d_in[0];
    const float* Kseq = (const float*)d_in[1];
    const float* WQ = (const float*)d_in[3];
    const float* WK = (const float*)d_in[4];
    const float* Wa = (const float*)d_in[5];
    const float* Wb = (const float*)d_in[6];
    const float* WP = (const float*)d_in[7];
    float* out = (float*)d_out;

    float *pQ, *pK, *pWQ, *pWK, *pWP, *pLA, *pLB, *pqg, *pkg;
    cudaGetSymbolAddress((void**)&pQ,  g_Q);
    cudaGetSymbolAddress((void**)&pK,  g_K);
    cudaGetSymbolAddress((void**)&pWQ, g_WQt);
    cudaGetSymbolAddress((void**)&pWK, g_WKt);
    cudaGetSymbolAddress((void**)&pWP, g_WPt);
    cudaGetSymbolAddress((void**)&pLA, g_logA);
    cudaGetSymbolAddress((void**)&pLB, g_logB);
    cudaGetSymbolAddress((void**)&pqg, g_qg);
    cudaGetSymbolAddress((void**)&pkg, g_kg);

    cudaFuncSetAttribute(gemm_mma<0>, cudaFuncAttributeMaxDynamicSharedMemorySize, GSMEM);
    cudaFuncSetAttribute(gemm_mma<2>, cudaFuncAttributeMaxDynamicSharedMemorySize, GSMEM);

    dim3 tg(32, 32), tb(32, 8);
    dim3 gg(Dc / 128, Mc / 128);

    tcvt_k<<<tg, tb>>>(WQ, pWQ);                                       // 1
    tcvt_k<<<tg, tb>>>(WK, pWK);                                       // 2
    tcvt_k<<<tg, tb>>>(WP, pWP);                                       // 3
    gemm_mma<0><<<gg, 128, GSMEM>>>(Qseq, pWQ, pQ, nullptr, nullptr);  // 4 <- profiled
    gemm_mma<0><<<gg, 128, GSMEM>>>(Kseq, pWK, pK, nullptr, nullptr);  // 5

    logitsA_k<<<Mc / 4 / 8, 256>>>(Wa);
    pool_k<<<Bc * Hc, 512>>>(pLA, pQ, nullptr, pqg);
    logitsB_k<<<Mc / 4 / 8, 256>>>(Wb);
    pool_k<<<Bc * Hc, 512>>>(pLB, pK, pqg, pkg);

    gemm_mma<2><<<gg, 128, GSMEM>>>(pQ, pWP, out, pQ, pkg);
}

// round 9
// speedup vs baseline: 1.4604x; 1.0181x over previous
#include <cuda_runtime.h>
#include <cstdint>

// ---------------------------------------------------------------------------
// Fastformer — tf32 mma.sync GEMMs; Q&K projections fused into one launch
// (grid.z=2) to absorb wave-quantization tails.
// ---------------------------------------------------------------------------

#define Bc 8
#define Sc 2048
#define Dc 1024
#define Hc 16
#define DHc 64
#define Mc (Bc * Sc)   // 16384

__device__ float g_Q[Mc * Dc];
__device__ float g_K[Mc * Dc];
__device__ float g_WQt[Dc * Dc];       // [n][k] transposed+tf32
__device__ float g_WKt[Dc * Dc];
__device__ float g_WPt[Dc * Dc];
__device__ float g_logA[Bc * Hc * Sc];
__device__ float g_logB[Bc * Hc * Sc];
__device__ float g_qg[Bc * Hc * DHc];
__device__ float g_kg[Bc * Dc];

// ===========================================================================
__device__ __forceinline__ uint32_t cvta_smem(const void* p) {
    uint32_t a;
    asm("{ .reg .u64 t; cvta.to.shared.u64 t, %1; cvt.u32.u64 %0, t; }" : "=r"(a) : "l"(p));
    return a;
}
__device__ __forceinline__ uint32_t f2tf(float x) {
    uint32_t u;
    asm("cvt.rna.tf32.f32 %0, %1;" : "=r"(u) : "f"(x));
    return u;
}
__device__ __forceinline__ float tff(float x) { return __uint_as_float(f2tf(x)); }

__device__ __forceinline__ void cp16(uint32_t s, const void* g) {
    asm volatile("cp.async.cg.shared.global [%0], [%1], 16;" :: "r"(s), "l"(g));
}
__device__ __forceinline__ void cp_commit() {
    asm volatile("cp.async.commit_group;" ::: "memory");
}
template <int N>
__device__ __forceinline__ void cp_wait() {
    asm volatile("cp.async.wait_group %0;" :: "n"(N) : "memory");
}
__device__ __forceinline__ void ldmx4(uint32_t& r0, uint32_t& r1, uint32_t& r2, uint32_t& r3,
                                      uint32_t addr) {
    asm volatile("ldmatrix.sync.aligned.m8n8.x4.shared.b16 {%0,%1,%2,%3}, [%4];"
                 : "=r"(r0), "=r"(r1), "=r"(r2), "=r"(r3) : "r"(addr));
}
__device__ __forceinline__ void mma_tf32(float& c0, float& c1, float& c2, float& c3,
                                         uint32_t a0, uint32_t a1, uint32_t a2, uint32_t a3,
                                         uint32_t b0, uint32_t b1) {
    asm volatile(
        "mma.sync.aligned.m16n8k8.row.col.f32.tf32.tf32.f32 "
        "{%0,%1,%2,%3}, {%4,%5,%6,%7}, {%8,%9}, {%0,%1,%2,%3};"
        : "+f"(c0), "+f"(c1), "+f"(c2), "+f"(c3)
        : "r"(a0), "r"(a1), "r"(a2), "r"(a3), "r"(b0), "r"(b1));
}

// ===========================================================================
// GEMM body: C[M,N] = A[M,K] @ Bt[N,K]^T.  BM=BN=128, BK=32, 128 thr
// (2x2 warps, 64x64 tiles), 2-stage cp.async, ldmatrix.x4, 3 CTAs/SM.
// SCALED=0: cvt A in-reg.  SCALED=1: scale A by Kg then cvt, += resid.
// ===========================================================================
#define TILEB (128 * 144)
#define STGB (2 * TILEB)
#define GSMEM (2 * STGB)            // 73728
#define NCH (Dc / 32)

template <int SCALED>
__device__ __forceinline__ void gemm_body(
    const float* __restrict__ A, const float* __restrict__ Bt,
    float* __restrict__ C, const float* __restrict__ resid,
    const float* __restrict__ Kg)
{
    extern __shared__ char smem[];
    const uint32_t sb = cvta_smem(smem);
    const int tid  = threadIdx.x;
    const int wid  = tid >> 5, lane = tid & 31;
    const int g    = lane >> 2, t = lane & 3;
    const int wm   = wid >> 1, wn = wid & 1;
    const int crow = blockIdx.y * 128, ccol = blockIdx.x * 128;

    const float* kgp = SCALED ? (Kg + (size_t)(crow / Sc) * Dc) : nullptr;

    const int lrow = tid >> 3, seg = tid & 7;
    const float* Ag = A  + (size_t)(crow + lrow) * Dc + seg * 4;
    const float* Bg = Bt + (size_t)(ccol + lrow) * Dc + seg * 4;
    const uint32_t sA = (uint32_t)(lrow * 144 + seg * 16);
    const uint32_t sB = (uint32_t)(TILEB + lrow * 144 + seg * 16);

    const int ltile = lane >> 3, lr = lane & 7;
    uint32_t offA[4], offB[4];
#pragma unroll
    for (int im = 0; im < 4; im++)
        offA[im] = (uint32_t)((wm * 64 + im * 16 + (ltile & 1) * 8 + lr) * 144 + (ltile >> 1) * 16);
#pragma unroll
    for (int j = 0; j < 4; j++)
        offB[j] = (uint32_t)(TILEB + (wn * 64 + j * 16 + (ltile & 1) * 8 + lr) * 144 + (ltile >> 1) * 16);

    float acc[4][8][4];
#pragma unroll
    for (int i = 0; i < 4; i++)
#pragma unroll
        for (int j = 0; j < 8; j++)
#pragma unroll
            for (int k = 0; k < 4; k++) acc[i][j][k] = 0.f;

    auto issue = [&](int c) {
        uint32_t base = sb + (uint32_t)(c & 1) * STGB;
        const float* ag = Ag + c * 32;
        const float* bg = Bg + c * 32;
#pragma unroll
        for (int rr = 0; rr < 8; rr++) {
            cp16(base + sA + rr * (16 * 144), ag + (size_t)rr * 16 * Dc);
            cp16(base + sB + rr * (16 * 144), bg + (size_t)rr * 16 * Dc);
        }
        cp_commit();
    };

    issue(0);

    for (int c = 0; c < NCH; c++) {
        cp_wait<0>();
        __syncthreads();
        if (c + 1 < NCH) issue(c + 1);

        const uint32_t base = sb + (uint32_t)(c & 1) * STGB;

        float kgs[8];
        if (SCALED) {
#pragma unroll
            for (int j = 0; j < 8; j++) kgs[j] = kgp[c * 32 + t + 4 * j];
        }

#pragma unroll
        for (int kk = 0; kk < 4; kk++) {
            uint32_t a[4][4], b[8][2];
#pragma unroll
            for (int im = 0; im < 4; im++)
                ldmx4(a[im][0], a[im][1], a[im][2], a[im][3], base + offA[im] + kk * 32);
#pragma unroll
            for (int j = 0; j < 4; j++) {
                uint32_t r0, r1, r2, r3;
                ldmx4(r0, r1, r2, r3, base + offB[j] + kk * 32);
                b[2 * j][0] = r0; b[2 * j + 1][0] = r1;
                b[2 * j][1] = r2; b[2 * j + 1][1] = r3;
            }
            if (SCALED) {
                const float s0 = kgs[2 * kk], s1 = kgs[2 * kk + 1];
#pragma unroll
                for (int im = 0; im < 4; im++) {
                    a[im][0] = f2tf(__uint_as_float(a[im][0]) * s0);
                    a[im][1] = f2tf(__uint_as_float(a[im][1]) * s0);
                    a[im][2] = f2tf(__uint_as_float(a[im][2]) * s1);
                    a[im][3] = f2tf(__uint_as_float(a[im][3]) * s1);
                }
            } else {
#pragma unroll
                for (int im = 0; im < 4; im++)
#pragma unroll
                    for (int r = 0; r < 4; r++)
                        a[im][r] = f2tf(__uint_as_float(a[im][r]));
            }
#pragma unroll
            for (int im = 0; im < 4; im++)
#pragma unroll
                for (int in = 0; in < 8; in++)
                    mma_tf32(acc[im][in][0], acc[im][in][1], acc[im][in][2], acc[im][in][3],
                             a[im][0], a[im][1], a[im][2], a[im][3],
                             b[in][0], b[in][1]);
        }
        __syncthreads();
    }

#pragma unroll
    for (int im = 0; im < 4; im++) {
#pragma unroll
        for (int in = 0; in < 8; in++) {
            const int r0 = crow + wm * 64 + im * 16 + g;
            const int cc = ccol + wn * 64 + in * 8 + 2 * t;
            float2 v0 = make_float2(acc[im][in][0], acc[im][in][1]);
            float2 v1 = make_float2(acc[im][in][2], acc[im][in][3]);
            if (SCALED) {
                float2 q0 = *(const float2*)(resid + (size_t)r0 * Dc + cc);
                float2 q1 = *(const float2*)(resid + (size_t)(r0 + 8) * Dc + cc);
                v0.x += q0.x; v0.y += q0.y; v1.x += q1.x; v1.y += q1.y;
            }
            *(float2*)(C + (size_t)r0 * Dc + cc) = v0;
            *(float2*)(C + (size_t)(r0 + 8) * Dc + cc) = v1;
        }
    }
}

// fused Q&K projection: blockIdx.z picks the problem
__global__ __launch_bounds__(128, 3)
void gemm_qk(const float* __restrict__ Aq, const float* __restrict__ Ak,
             const float* __restrict__ Bq, const float* __restrict__ Bk,
             float* __restrict__ Cq, float* __restrict__ Ck)
{
    if (blockIdx.z == 0) gemm_body<0>(Aq, Bq, Cq, nullptr, nullptr);
    else                 gemm_body<0>(Ak, Bk, Ck, nullptr, nullptr);
}

__global__ __launch_bounds__(128, 3)
void gemm_out(const float* __restrict__ A, const float* __restrict__ Bt,
              float* __restrict__ C, const float* __restrict__ resid,
              const float* __restrict__ Kg)
{
    gemm_body<1>(A, Bt, C, resid, Kg);
}

// ===========================================================================
__global__ void tcvt_k(const float* __restrict__ W, float* __restrict__ Wt)
{
    __shared__ float tbuf[32][33];
    int n0 = blockIdx.x * 32, k0 = blockIdx.y * 32;
    int tx = threadIdx.x, ty = threadIdx.y;
#pragma unroll
    for (int i = 0; i < 32; i += 8) tbuf[ty + i][tx] = W[(size_t)(k0 + ty + i) * Dc + n0 + tx];
    __syncthreads();
#pragma unroll
    for (int i = 0; i < 32; i += 8)
        Wt[(size_t)(n0 + ty + i) * Dc + k0 + tx] = tff(tbuf[tx][ty + i]);
}

// ===========================================================================
// logitsA: one warp per 4 rows
// ===========================================================================
__global__ void logitsA_k(const float* __restrict__ Wa)
{
    int gw = (blockIdx.x * blockDim.x + threadIdx.x) >> 5;
    int lane = threadIdx.x & 31;
    int b = gw >> 9;
    int s0 = (gw << 2) & 2047;
    const float* q = g_Q + ((size_t)gw << 2) * Dc;

    float acc[4][16];
#pragma unroll
    for (int r = 0; r < 4; r++)
#pragma unroll
        for (int e = 0; e < 16; e++) acc[r][e] = 0.f;

    for (int i = 0; i < 8; i++) {
        int d4 = lane + 32 * i;
        float4 qv[4];
#pragma unroll
        for (int r = 0; r < 4; r++)
            qv[r] = reinterpret_cast<const float4*>(q + (size_t)r * Dc)[d4];
        const float4* wa = reinterpret_cast<const float4*>(Wa) + (size_t)d4 * 16;
#pragma unroll
        for (int dd = 0; dd < 4; dd++) {
            float4 w0 = wa[dd * 4 + 0], w1 = wa[dd * 4 + 1];
            float4 w2 = wa[dd * 4 + 2], w3 = wa[dd * 4 + 3];
            float qs[4];
            qs[0] = (dd == 0) ? qv[0].x : (dd == 1) ? qv[0].y : (dd == 2) ? qv[0].z : qv[0].w;
            qs[1] = (dd == 0) ? qv[1].x : (dd == 1) ? qv[1].y : (dd == 2) ? qv[1].z : qv[1].w;
            qs[2] = (dd == 0) ? qv[2].x : (dd == 1) ? qv[2].y : (dd == 2) ? qv[2].z : qv[2].w;
            qs[3] = (dd == 0) ? qv[3].x : (dd == 1) ? qv[3].y : (dd == 2) ? qv[3].z : qv[3].w;
#pragma unroll
            for (int r = 0; r < 4; r++) {
                acc[r][0]  += qs[r] * w0.x; acc[r][1]  += qs[r] * w0.y;
                acc[r][2]  += qs[r] * w0.z; acc[r][3]  += qs[r] * w0.w;
                acc[r][4]  += qs[r] * w1.x; acc[r][5]  += qs[r] * w1.y;
                acc[r][6]  += qs[r] * w1.z; acc[r][7]  += qs[r] * w1.w;
                acc[r][8]  += qs[r] * w2.x; acc[r][9]  += qs[r] * w2.y;
                acc[r][10] += qs[r] * w2.z; acc[r][11] += qs[r] * w2.w;
                acc[r][12] += qs[r] * w3.x; acc[r][13] += qs[r] * w3.y;
                acc[r][14] += qs[r] * w3.z; acc[r][15] += qs[r] * w3.w;
            }
        }
    }

#pragma unroll
    for (int e = 0; e < 16; e++) {
        float v0 = acc[0][e], v1 = acc[1][e], v2 = acc[2][e], v3 = acc[3][e];
#pragma unroll
        for (int o = 16; o; o >>= 1) {
            v0 += __shfl_xor_sync(0xffffffffu, v0, o);
            v1 += __shfl_xor_sync(0xffffffffu, v1, o);
            v2 += __shfl_xor_sync(0xffffffffu, v2, o);
            v3 += __shfl_xor_sync(0xffffffffu, v3, o);
        }
        if (lane == e) {
            float* dst = g_logA + (b * Hc + e) * Sc + s0;
            dst[0] = v0 * 0.125f; dst[1] = v1 * 0.125f;
            dst[2] = v2 * 0.125f; dst[3] = v3 * 0.125f;
        }
    }
}

// ===========================================================================
// logitsB: one warp per 4 scrambled rows
// ===========================================================================
__global__ void logitsB_k(const float* __restrict__ Wb)
{
    int gw = (blockIdx.x * blockDim.x + threadIdx.x) >> 5;
    int lane = threadIdx.x & 31;
    int b = gw >> 9;
    int spL = (gw << 2) & 2047;
    int h0 = spL >> 7;
    int s0 = (spL & 127) << 4;

    const float* qgv = g_qg + (b * Hc + h0) * DHc;
    const float* Kb  = g_K + ((size_t)(b * Sc + s0)) * Dc + h0 * DHc;

    float acc[4][16];
#pragma unroll
    for (int r = 0; r < 4; r++)
#pragma unroll
        for (int e = 0; e < 16; e++) acc[r][e] = 0.f;

    for (int i = 0; i < 32; i++) {
        int k = lane + 32 * i;
        int tt = k >> 6, j = k & 63;
        float qv = qgv[j];
        float vr[4];
#pragma unroll
        for (int r = 0; r < 4; r++)
            vr[r] = Kb[(size_t)(r * 16 + tt) * Dc + j] * qv;
        const float4* w4 = reinterpret_cast<const float4*>(Wb + k * 16);
        float4 w0 = w4[0], w1 = w4[1], w2 = w4[2], w3 = w4[3];
#pragma unroll
        for (int r = 0; r < 4; r++) {
            acc[r][0]  += vr[r] * w0.x; acc[r][1]  += vr[r] * w0.y;
            acc[r][2]  += vr[r] * w0.z; acc[r][3]  += vr[r] * w0.w;
            acc[r][4]  += vr[r] * w1.x; acc[r][5]  += vr[r] * w1.y;
            acc[r][6]  += vr[r] * w1.z; acc[r][7]  += vr[r] * w1.w;
            acc[r][8]  += vr[r] * w2.x; acc[r][9]  += vr[r] * w2.y;
            acc[r][10] += vr[r] * w2.z; acc[r][11] += vr[r] * w2.w;
            acc[r][12] += vr[r] * w3.x; acc[r][13] += vr[r] * w3.y;
            acc[r][14] += vr[r] * w3.z; acc[r][15] += vr[r] * w3.w;
        }
    }

#pragma unroll
    for (int e = 0; e < 16; e++) {
        float v0 = acc[0][e], v1 = acc[1][e], v2 = acc[2][e], v3 = acc[3][e];
#pragma unroll
        for (int o = 16; o; o >>= 1) {
            v0 += __shfl_xor_sync(0xffffffffu, v0, o);
            v1 += __shfl_xor_sync(0xffffffffu, v1, o);
            v2 += __shfl_xor_sync(0xffffffffu, v2, o);
            v3 += __shfl_xor_sync(0xffffffffu, v3, o);
        }
        if (lane == e) {
            float* dst = g_logB + (b * Hc + e) * Sc + spL;
            dst[0] = v0 * 0.125f; dst[1] = v1 * 0.125f;
            dst[2] = v2 * 0.125f; dst[3] = v3 * 0.125f;
        }
    }
}

// ===========================================================================
__global__ void pool_k(const float* __restrict__ logits, const float* __restrict__ X,
                       const float* __restrict__ qscale, float* __restrict__ out)
{
    int bh = blockIdx.x;
    int b = bh >> 4, h = bh & 15;
    const float* lg = logits + bh * Sc;

    __shared__ float sE[Sc];
    __shared__ float red[16];
    __shared__ float part[8][DHc];

    int tid = threadIdx.x, lane = tid & 31, warp = tid >> 5;

    float mx = -1e30f;
    for (int s = tid; s < Sc; s += 512) mx = fmaxf(mx, lg[s]);
#pragma unroll
    for (int o = 16; o; o >>= 1) mx = fmaxf(mx, __shfl_xor_sync(0xffffffffu, mx, o));
    if (lane == 0) red[warp] = mx;
    __syncthreads();
    mx = red[0];
#pragma unroll
    for (int i = 1; i < 16; i++) mx = fmaxf(mx, red[i]);
    __syncthreads();

    float sum = 0.f;
    for (int s = tid; s < Sc; s += 512) {
        float e = __expf(lg[s] - mx);
        sE[s] = e;
        sum += e;
    }
#pragma unroll
    for (int o = 16; o; o >>= 1) sum += __shfl_xor_sync(0xffffffffu, sum, o);
    if (lane == 0) red[warp] = sum;
    __syncthreads();
    float tot = 0.f;
#pragma unroll
    for (int i = 0; i < 16; i++) tot += red[i];
    float inv = 1.0f / tot;

    int j = tid & 63, gg = tid >> 6;
    const float* Xb = X + ((size_t)b * Sc) * Dc + h * DHc + j;
    float a0 = 0.f, a1 = 0.f, a2 = 0.f, a3 = 0.f;
    for (int s = gg; s < Sc; s += 32) {
        a0 += sE[s]      * Xb[(size_t)s * Dc];
        a1 += sE[s + 8]  * Xb[(size_t)(s + 8)  * Dc];
        a2 += sE[s + 16] * Xb[(size_t)(s + 16) * Dc];
        a3 += sE[s + 24] * Xb[(size_t)(s + 24) * Dc];
    }
    part[gg][j] = (a0 + a1) + (a2 + a3);
    __syncthreads();
    if (gg == 0) {
        float v = 0.f;
#pragma unroll
        for (int i = 0; i < 8; i++) v += part[i][j];
        v *= inv;
        if (qscale) v *= qscale[bh * DHc + j];
        out[bh * DHc + j] = v;
    }
}

// ===========================================================================
extern "C" void kernel_launch(void* const* d_in, const int* in_sizes, int n_in,
                              void* d_out, int out_size)
{
    const float* Qseq = (const float*)d_in[0];
    const float* Kseq = (const float*)d_in[1];
    const float* WQ = (const float*)d_in[3];
    const float* WK = (const float*)d_in[4];
    const float* Wa = (const float*)d_in[5];
    const float* Wb = (const float*)d_in[6];
    const float* WP = (const float*)d_in[7];
    float* out = (float*)d_out;

    float *pQ, *pK, *pWQ, *pWK, *pWP, *pLA, *pLB, *pqg, *pkg;
    cudaGetSymbolAddress((void**)&pQ,  g_Q);
    cudaGetSymbolAddress((void**)&pK,  g_K);
    cudaGetSymbolAddress((void**)&pWQ, g_WQt);
    cudaGetSymbolAddress((void**)&pWK, g_WKt);
    cudaGetSymbolAddress((void**)&pWP, g_WPt);
    cudaGetSymbolAddress((void**)&pLA, g_logA);
    cudaGetSymbolAddress((void**)&pLB, g_logB);
    cudaGetSymbolAddress((void**)&pqg, g_qg);
    cudaGetSymbolAddress((void**)&pkg, g_kg);

    cudaFuncSetAttribute(gemm_qk,  cudaFuncAttributeMaxDynamicSharedMemorySize, GSMEM);
    cudaFuncSetAttribute(gemm_out, cudaFuncAttributeMaxDynamicSharedMemorySize, GSMEM);

    dim3 tg(32, 32), tb(32, 8);
    dim3 ggqk(Dc / 128, Mc / 128, 2);   // fused Q+K projection
    dim3 gg(Dc / 128, Mc / 128);

    tcvt_k<<<tg, tb>>>(WQ, pWQ);                                   // 1
    tcvt_k<<<tg, tb>>>(WK, pWK);                                   // 2
    tcvt_k<<<tg, tb>>>(WP, pWP);                                   // 3
    gemm_qk<<<ggqk, 128, GSMEM>>>(Qseq, Kseq, pWQ, pWK, pQ, pK);   // 4 <- profiled

    logitsA_k<<<Mc / 4 / 8, 256>>>(Wa);
    pool_k<<<Bc * Hc, 512>>>(pLA, pQ, nullptr, pqg);
    logitsB_k<<<Mc / 4 / 8, 256>>>(Wb);
    pool_k<<<Bc * Hc, 512>>>(pLB, pK, pqg, pkg);

    gemm_out<<<gg, 128, GSMEM>>>(pQ, pWP, out, pQ, pkg);
}

// round 11
// speedup vs baseline: 2.3643x; 1.6190x over previous
#include <cuda_runtime.h>
#include <cuda_fp16.h>
#include <cstdint>

// ---------------------------------------------------------------------------
// Fastformer — fp16 mma.sync (m16n8k16) GEMMs, fp16 weights via cp.async,
// fp32 activations converted in the loader. 64x64 warp tiles, 2-stage.
// RSTRIDE=80 (16B-aligned, ldmatrix conflict-free).
// ---------------------------------------------------------------------------

#define Bc 8
#define Sc 2048
#define Dc 1024
#define Hc 16
#define DHc 64
#define Mc (Bc * Sc)   // 16384

__device__ float  g_Q[Mc * Dc];
__device__ float  g_K[Mc * Dc];
__device__ __half g_WQt[Dc * Dc];       // [n][k] transposed fp16 weights
__device__ __half g_WKt[Dc * Dc];
__device__ __half g_WPt[Dc * Dc];
__device__ float  g_logA[Bc * Hc * Sc];
__device__ float  g_logB[Bc * Hc * Sc];
__device__ float  g_qg[Bc * Hc * DHc];
__device__ float  g_kg[Bc * Dc];

// ===========================================================================
__device__ __forceinline__ uint32_t cvta_smem(const void* p) {
    uint32_t a;
    asm("{ .reg .u64 t; cvta.to.shared.u64 t, %1; cvt.u32.u64 %0, t; }" : "=r"(a) : "l"(p));
    return a;
}
__device__ __forceinline__ void cp16(uint32_t s, const void* g) {
    asm volatile("cp.async.cg.shared.global [%0], [%1], 16;" :: "r"(s), "l"(g));
}
__device__ __forceinline__ void cp_commit() {
    asm volatile("cp.async.commit_group;" ::: "memory");
}
template <int N>
__device__ __forceinline__ void cp_wait() {
    asm volatile("cp.async.wait_group %0;" :: "n"(N) : "memory");
}
__device__ __forceinline__ void ldmx4(uint32_t& r0, uint32_t& r1, uint32_t& r2, uint32_t& r3,
                                      uint32_t addr) {
    asm volatile("ldmatrix.sync.aligned.m8n8.x4.shared.b16 {%0,%1,%2,%3}, [%4];"
                 : "=r"(r0), "=r"(r1), "=r"(r2), "=r"(r3) : "r"(addr));
}
__device__ __forceinline__ void sts64(uint32_t addr, uint32_t u0, uint32_t u1) {
    asm volatile("st.shared.v2.u32 [%0], {%1,%2};" :: "r"(addr), "r"(u0), "r"(u1) : "memory");
}
__device__ __forceinline__ void mma_f16(float& c0, float& c1, float& c2, float& c3,
                                        uint32_t a0, uint32_t a1, uint32_t a2, uint32_t a3,
                                        uint32_t b0, uint32_t b1) {
    asm volatile(
        "mma.sync.aligned.m16n8k16.row.col.f32.f16.f16.f32 "
        "{%0,%1,%2,%3}, {%4,%5,%6,%7}, {%8,%9}, {%0,%1,%2,%3};"
        : "+f"(c0), "+f"(c1), "+f"(c2), "+f"(c3)
        : "r"(a0), "r"(a1), "r"(a2), "r"(a3), "r"(b0), "r"(b1));
}
__device__ __forceinline__ uint32_t pack_h2(float x, float y) {
    __half2 h = __floats2half2_rn(x, y);   // x -> low, y -> high
    return *reinterpret_cast<uint32_t*>(&h);
}

// ===========================================================================
// GEMM: C[M,N] = A[M,K](fp32) @ Bt[N,K](fp16)^T.  BM=BN=128, BK=32,
// 128 thr (2x2 warps, 64x64 tiles), fp16 m16n8k16 mma, 2-stage.
// A: LDG float4 prefetch -> fp16 STS.  B: cp.async (already fp16).
// SCALED=1: A scaled by Kg[b,k] before fp16 cvt; epilogue += resid.
// smem row stride 80B (64B data + 16B pad): 16B-aligned, conflict-free
// ldmatrix phases (80*lr mod 128 covers all eight 16B banks).
// ===========================================================================
#define RSTRIDE 80
#define TILEB (128 * RSTRIDE)       // 10240 bytes per matrix tile
#define STGB (2 * TILEB)            // 20480
#define GSMEM (2 * STGB)            // 40960
#define NCH (Dc / 32)               // 32

template <int SCALED>
__device__ __forceinline__ void gemm_body(
    const float* __restrict__ A, const __half* __restrict__ Bt,
    float* __restrict__ C, const float* __restrict__ resid,
    const float* __restrict__ Kg)
{
    extern __shared__ char smem[];
    const uint32_t sb = cvta_smem(smem);
    const int tid  = threadIdx.x;
    const int wid  = tid >> 5, lane = tid & 31;
    const int g    = lane >> 2, t = lane & 3;
    const int wm   = wid >> 1, wn = wid & 1;
    const int crow = blockIdx.y * 128, ccol = blockIdx.x * 128;

    const float* kgp = SCALED ? (Kg + (size_t)(crow / Sc) * Dc) : nullptr;

    // A loader: 8 thr/row (16B fp32 each), 16 rows/pass, 8 passes
    const int arow = tid >> 3, acol = (tid & 7) * 4;
    const float* Ag = A + (size_t)(crow + arow) * Dc + acol;
    const uint32_t sAaddr = sb + (uint32_t)(arow * RSTRIDE + (tid & 7) * 8);

    // B loader: 4 thr/row (16B fp16 each), 32 rows/pass, 4 passes
    const int brow = tid >> 2, bgran = tid & 3;
    const __half* Bg = Bt + (size_t)(ccol + brow) * Dc + bgran * 8;
    const uint32_t sBaddr = sb + TILEB + (uint32_t)(brow * RSTRIDE + bgran * 16);

    // ldmatrix per-lane offsets
    const int ltile = lane >> 3, lr = lane & 7;
    uint32_t offA[4], offB[4];
#pragma unroll
    for (int im = 0; im < 4; im++)
        offA[im] = (uint32_t)((wm * 64 + im * 16 + (ltile & 1) * 8 + lr) * RSTRIDE
                              + (ltile >> 1) * 16);
#pragma unroll
    for (int j = 0; j < 4; j++)
        offB[j] = (uint32_t)(TILEB + (wn * 64 + j * 16 + (ltile >> 1) * 8 + lr) * RSTRIDE
                             + (ltile & 1) * 16);

    float acc[4][8][4];
#pragma unroll
    for (int i = 0; i < 4; i++)
#pragma unroll
        for (int j = 0; j < 8; j++)
#pragma unroll
            for (int k = 0; k < 4; k++) acc[i][j][k] = 0.f;

    float4 areg[8];

    auto ldgA = [&](int c) {
#pragma unroll
        for (int p = 0; p < 8; p++)
            areg[p] = *reinterpret_cast<const float4*>(Ag + (size_t)p * 16 * Dc + c * 32);
    };
    auto stsA = [&](int c) {
        uint32_t base = sAaddr + (uint32_t)(c & 1) * STGB;
        float4 kgv;
        if (SCALED) kgv = *reinterpret_cast<const float4*>(kgp + c * 32 + acol);
#pragma unroll
        for (int p = 0; p < 8; p++) {
            float4 v = areg[p];
            if (SCALED) { v.x *= kgv.x; v.y *= kgv.y; v.z *= kgv.z; v.w *= kgv.w; }
            sts64(base + p * 16 * RSTRIDE, pack_h2(v.x, v.y), pack_h2(v.z, v.w));
        }
    };
    auto issueB = [&](int c) {
        uint32_t base = sBaddr + (uint32_t)(c & 1) * STGB;
        const __half* bg = Bg + c * 32;
#pragma unroll
        for (int p = 0; p < 4; p++)
            cp16(base + p * 32 * RSTRIDE, bg + (size_t)p * 32 * Dc);
        cp_commit();
    };

    ldgA(0);
    issueB(0);

    for (int c = 0; c < NCH; c++) {
        stsA(c);                     // writes stage c&1
        cp_wait<0>();                // B stage c arrived
        __syncthreads();             // A STS visible; all warps done with other stage
        if (c + 1 < NCH) { ldgA(c + 1); issueB(c + 1); }

        const uint32_t base = sb + (uint32_t)(c & 1) * STGB;

#pragma unroll
        for (int kk = 0; kk < 2; kk++) {     // 16 k-values per kk
            uint32_t a[4][4], b[8][2];
#pragma unroll
            for (int im = 0; im < 4; im++)
                ldmx4(a[im][0], a[im][1], a[im][2], a[im][3],
                      base + offA[im] + kk * 32);
#pragma unroll
            for (int j = 0; j < 4; j++) {
                uint32_t r0, r1, r2, r3;
                ldmx4(r0, r1, r2, r3, base + offB[j] + kk * 32);
                b[2 * j][0] = r0;     b[2 * j][1] = r1;      // n0-7:  {k0-7, k8-15}
                b[2 * j + 1][0] = r2; b[2 * j + 1][1] = r3;  // n8-15: {k0-7, k8-15}
            }
#pragma unroll
            for (int im = 0; im < 4; im++)
#pragma unroll
                for (int in = 0; in < 8; in++)
                    mma_f16(acc[im][in][0], acc[im][in][1], acc[im][in][2], acc[im][in][3],
                            a[im][0], a[im][1], a[im][2], a[im][3],
                            b[in][0], b[in][1]);
        }
    }
    __syncthreads();

    // epilogue (fragment rows g, g+8; cols 2t, 2t+1)
#pragma unroll
    for (int im = 0; im < 4; im++) {
#pragma unroll
        for (int in = 0; in < 8; in++) {
            const int r0 = crow + wm * 64 + im * 16 + g;
            const int cc = ccol + wn * 64 + in * 8 + 2 * t;
            float2 v0 = make_float2(acc[im][in][0], acc[im][in][1]);
            float2 v1 = make_float2(acc[im][in][2], acc[im][in][3]);
            if (SCALED) {
                float2 q0 = *(const float2*)(resid + (size_t)r0 * Dc + cc);
                float2 q1 = *(const float2*)(resid + (size_t)(r0 + 8) * Dc + cc);
                v0.x += q0.x; v0.y += q0.y; v1.x += q1.x; v1.y += q1.y;
            }
            *(float2*)(C + (size_t)r0 * Dc + cc) = v0;
            *(float2*)(C + (size_t)(r0 + 8) * Dc + cc) = v1;
        }
    }
}

// fused Q&K projection: blockIdx.z picks the problem
__global__ __launch_bounds__(128, 2)
void gemm_qk(const float* __restrict__ Aq, const float* __restrict__ Ak,
             const __half* __restrict__ Bq, const __half* __restrict__ Bk,
             float* __restrict__ Cq, float* __restrict__ Ck)
{
    if (blockIdx.z == 0) gemm_body<0>(Aq, Bq, Cq, nullptr, nullptr);
    else                 gemm_body<0>(Ak, Bk, Ck, nullptr, nullptr);
}

__global__ __launch_bounds__(128, 2)
void gemm_out(const float* __restrict__ A, const __half* __restrict__ Bt,
              float* __restrict__ C, const float* __restrict__ resid,
              const float* __restrict__ Kg)
{
    gemm_body<1>(A, Bt, C, resid, Kg);
}

// ===========================================================================
// weight transpose + fp16: Wt[n][k] = half(W[k][n])
// ===========================================================================
__global__ void tcvt_k(const float* __restrict__ W, __half* __restrict__ Wt)
{
    __shared__ float tbuf[32][33];
    int n0 = blockIdx.x * 32, k0 = blockIdx.y * 32;
    int tx = threadIdx.x, ty = threadIdx.y;
#pragma unroll
    for (int i = 0; i < 32; i += 8) tbuf[ty + i][tx] = W[(size_t)(k0 + ty + i) * Dc + n0 + tx];
    __syncthreads();
#pragma unroll
    for (int i = 0; i < 32; i += 8)
        Wt[(size_t)(n0 + ty + i) * Dc + k0 + tx] = __float2half_rn(tbuf[tx][ty + i]);
}

// ===========================================================================
// logitsA: one warp per 4 rows
// ===========================================================================
__global__ void logitsA_k(const float* __restrict__ Wa)
{
    int gw = (blockIdx.x * blockDim.x + threadIdx.x) >> 5;
    int lane = threadIdx.x & 31;
    int b = gw >> 9;
    int s0 = (gw << 2) & 2047;
    const float* q = g_Q + ((size_t)gw << 2) * Dc;

    float acc[4][16];
#pragma unroll
    for (int r = 0; r < 4; r++)
#pragma unroll
        for (int e = 0; e < 16; e++) acc[r][e] = 0.f;

    for (int i = 0; i < 8; i++) {
        int d4 = lane + 32 * i;
        float4 qv[4];
#pragma unroll
        for (int r = 0; r < 4; r++)
            qv[r] = reinterpret_cast<const float4*>(q + (size_t)r * Dc)[d4];
        const float4* wa = reinterpret_cast<const float4*>(Wa) + (size_t)d4 * 16;
#pragma unroll
        for (int dd = 0; dd < 4; dd++) {
            float4 w0 = wa[dd * 4 + 0], w1 = wa[dd * 4 + 1];
            float4 w2 = wa[dd * 4 + 2], w3 = wa[dd * 4 + 3];
            float qs[4];
            qs[0] = (dd == 0) ? qv[0].x : (dd == 1) ? qv[0].y : (dd == 2) ? qv[0].z : qv[0].w;
            qs[1] = (dd == 0) ? qv[1].x : (dd == 1) ? qv[1].y : (dd == 2) ? qv[1].z : qv[1].w;
            qs[2] = (dd == 0) ? qv[2].x : (dd == 1) ? qv[2].y : (dd == 2) ? qv[2].z : qv[2].w;
            qs[3] = (dd == 0) ? qv[3].x : (dd == 1) ? qv[3].y : (dd == 2) ? qv[3].z : qv[3].w;
#pragma unroll
            for (int r = 0; r < 4; r++) {
                acc[r][0]  += qs[r] * w0.x; acc[r][1]  += qs[r] * w0.y;
                acc[r][2]  += qs[r] * w0.z; acc[r][3]  += qs[r] * w0.w;
                acc[r][4]  += qs[r] * w1.x; acc[r][5]  += qs[r] * w1.y;
                acc[r][6]  += qs[r] * w1.z; acc[r][7]  += qs[r] * w1.w;
                acc[r][8]  += qs[r] * w2.x; acc[r][9]  += qs[r] * w2.y;
                acc[r][10] += qs[r] * w2.z; acc[r][11] += qs[r] * w2.w;
                acc[r][12] += qs[r] * w3.x; acc[r][13] += qs[r] * w3.y;
                acc[r][14] += qs[r] * w3.z; acc[r][15] += qs[r] * w3.w;
            }
        }
    }

#pragma unroll
    for (int e = 0; e < 16; e++) {
        float v0 = acc[0][e], v1 = acc[1][e], v2 = acc[2][e], v3 = acc[3][e];
#pragma unroll
        for (int o = 16; o; o >>= 1) {
            v0 += __shfl_xor_sync(0xffffffffu, v0, o);
            v1 += __shfl_xor_sync(0xffffffffu, v1, o);
            v2 += __shfl_xor_sync(0xffffffffu, v2, o);
            v3 += __shfl_xor_sync(0xffffffffu, v3, o);
        }
        if (lane == e) {
            float* dst = g_logA + (b * Hc + e) * Sc + s0;
            dst[0] = v0 * 0.125f; dst[1] = v1 * 0.125f;
            dst[2] = v2 * 0.125f; dst[3] = v3 * 0.125f;
        }
    }
}

// ===========================================================================
// logitsB: one warp per 4 scrambled rows
// ===========================================================================
__global__ void logitsB_k(const float* __restrict__ Wb)
{
    int gw = (blockIdx.x * blockDim.x + threadIdx.x) >> 5;
    int lane = threadIdx.x & 31;
    int b = gw >> 9;
    int spL = (gw << 2) & 2047;
    int h0 = spL >> 7;
    int s0 = (spL & 127) << 4;

    const float* qgv = g_qg + (b * Hc + h0) * DHc;
    const float* Kb  = g_K + ((size_t)(b * Sc + s0)) * Dc + h0 * DHc;

    float acc[4][16];
#pragma unroll
    for (int r = 0; r < 4; r++)
#pragma unroll
        for (int e = 0; e < 16; e++) acc[r][e] = 0.f;

    for (int i = 0; i < 32; i++) {
        int k = lane + 32 * i;
        int tt = k >> 6, j = k & 63;
        float qv = qgv[j];
        float vr[4];
#pragma unroll
        for (int r = 0; r < 4; r++)
            vr[r] = Kb[(size_t)(r * 16 + tt) * Dc + j] * qv;
        const float4* w4 = reinterpret_cast<const float4*>(Wb + k * 16);
        float4 w0 = w4[0], w1 = w4[1], w2 = w4[2], w3 = w4[3];
#pragma unroll
        for (int r = 0; r < 4; r++) {
            acc[r][0]  += vr[r] * w0.x; acc[r][1]  += vr[r] * w0.y;
            acc[r][2]  += vr[r] * w0.z; acc[r][3]  += vr[r] * w0.w;
            acc[r][4]  += vr[r] * w1.x; acc[r][5]  += vr[r] * w1.y;
            acc[r][6]  += vr[r] * w1.z; acc[r][7]  += vr[r] * w1.w;
            acc[r][8]  += vr[r] * w2.x; acc[r][9]  += vr[r] * w2.y;
            acc[r][10] += vr[r] * w2.z; acc[r][11] += vr[r] * w2.w;
            acc[r][12] += vr[r] * w3.x; acc[r][13] += vr[r] * w3.y;
            acc[r][14] += vr[r] * w3.z; acc[r][15] += vr[r] * w3.w;
        }
    }

#pragma unroll
    for (int e = 0; e < 16; e++) {
        float v0 = acc[0][e], v1 = acc[1][e], v2 = acc[2][e], v3 = acc[3][e];
#pragma unroll
        for (int o = 16; o; o >>= 1) {
            v0 += __shfl_xor_sync(0xffffffffu, v0, o);
            v1 += __shfl_xor_sync(0xffffffffu, v1, o);
            v2 += __shfl_xor_sync(0xffffffffu, v2, o);
            v3 += __shfl_xor_sync(0xffffffffu, v3, o);
        }
        if (lane == e) {
            float* dst = g_logB + (b * Hc + e) * Sc + spL;
            dst[0] = v0 * 0.125f; dst[1] = v1 * 0.125f;
            dst[2] = v2 * 0.125f; dst[3] = v3 * 0.125f;
        }
    }
}

// ===========================================================================
__global__ void pool_k(const float* __restrict__ logits, const float* __restrict__ X,
                       const float* __restrict__ qscale, float* __restrict__ out)
{
    int bh = blockIdx.x;
    int b = bh >> 4, h = bh & 15;
    const float* lg = logits + bh * Sc;

    __shared__ float sE[Sc];
    __shared__ float red[16];
    __shared__ float part[8][DHc];

    int tid = threadIdx.x, lane = tid & 31, warp = tid >> 5;

    float mx = -1e30f;
    for (int s = tid; s < Sc; s += 512) mx = fmaxf(mx, lg[s]);
#pragma unroll
    for (int o = 16; o; o >>= 1) mx = fmaxf(mx, __shfl_xor_sync(0xffffffffu, mx, o));
    if (lane == 0) red[warp] = mx;
    __syncthreads();
    mx = red[0];
#pragma unroll
    for (int i = 1; i < 16; i++) mx = fmaxf(mx, red[i]);
    __syncthreads();

    float sum = 0.f;
    for (int s = tid; s < Sc; s += 512) {
        float e = __expf(lg[s] - mx);
        sE[s] = e;
        sum += e;
    }
#pragma unroll
    for (int o = 16; o; o >>= 1) sum += __shfl_xor_sync(0xffffffffu, sum, o);
    if (lane == 0) red[warp] = sum;
    __syncthreads();
    float tot = 0.f;
#pragma unroll
    for (int i = 0; i < 16; i++) tot += red[i];
    float inv = 1.0f / tot;

    int j = tid & 63, gg = tid >> 6;
    const float* Xb = X + ((size_t)b * Sc) * Dc + h * DHc + j;
    float a0 = 0.f, a1 = 0.f, a2 = 0.f, a3 = 0.f;
    for (int s = gg; s < Sc; s += 32) {
        a0 += sE[s]      * Xb[(size_t)s * Dc];
        a1 += sE[s + 8]  * Xb[(size_t)(s + 8)  * Dc];
        a2 += sE[s + 16] * Xb[(size_t)(s + 16) * Dc];
        a3 += sE[s + 24] * Xb[(size_t)(s + 24) * Dc];
    }
    part[gg][j] = (a0 + a1) + (a2 + a3);
    __syncthreads();
    if (gg == 0) {
        float v = 0.f;
#pragma unroll
        for (int i = 0; i < 8; i++) v += part[i][j];
        v *= inv;
        if (qscale) v *= qscale[bh * DHc + j];
        out[bh * DHc + j] = v;
    }
}

// ===========================================================================
extern "C" void kernel_launch(void* const* d_in, const int* in_sizes, int n_in,
                              void* d_out, int out_size)
{
    const float* Qseq = (const float*)d_in[0];
    const float* Kseq = (const float*)d_in[1];
    const float* WQ = (const float*)d_in[3];
    const float* WK = (const float*)d_in[4];
    const float* Wa = (const float*)d_in[5];
    const float* Wb = (const float*)d_in[6];
    const float* WP = (const float*)d_in[7];
    float* out = (float*)d_out;

    float *pQ, *pK, *pLA, *pLB, *pqg, *pkg;
    __half *pWQ, *pWK, *pWP;
    cudaGetSymbolAddress((void**)&pQ,  g_Q);
    cudaGetSymbolAddress((void**)&pK,  g_K);
    cudaGetSymbolAddress((void**)&pWQ, g_WQt);
    cudaGetSymbolAddress((void**)&pWK, g_WKt);
    cudaGetSymbolAddress((void**)&pWP, g_WPt);
    cudaGetSymbolAddress((void**)&pLA, g_logA);
    cudaGetSymbolAddress((void**)&pLB, g_logB);
    cudaGetSymbolAddress((void**)&pqg, g_qg);
    cudaGetSymbolAddress((void**)&pkg, g_kg);

    cudaFuncSetAttribute(gemm_qk,  cudaFuncAttributeMaxDynamicSharedMemorySize, GSMEM);
    cudaFuncSetAttribute(gemm_out, cudaFuncAttributeMaxDynamicSharedMemorySize, GSMEM);

    dim3 tg(32, 32), tb(32, 8);
    dim3 ggqk(Dc / 128, Mc / 128, 2);
    dim3 gg(Dc / 128, Mc / 128);

    tcvt_k<<<tg, tb>>>(WQ, pWQ);                                   // 1
    tcvt_k<<<tg, tb>>>(WK, pWK);                                   // 2
    tcvt_k<<<tg, tb>>>(WP, pWP);                                   // 3
    gemm_qk<<<ggqk, 128, GSMEM>>>(Qseq, Kseq, pWQ, pWK, pQ, pK);   // 4 <- profiled

    logitsA_k<<<Mc / 4 / 8, 256>>>(Wa);
    pool_k<<<Bc * Hc, 512>>>(pLA, pQ, nullptr, pqg);
    logitsB_k<<<Mc / 4 / 8, 256>>>(Wb);
    pool_k<<<Bc * Hc, 512>>>(pLB, pK, pqg, pkg);

    gemm_out<<<gg, 128, GSMEM>>>(pQ, pWP, out, pQ, pkg);
}

// round 12
// speedup vs baseline: 2.3800x; 1.0066x over previous
#include <cuda_runtime.h>
#include <cuda_fp16.h>
#include <cstdint>

// ---------------------------------------------------------------------------
// Fastformer — fp16 SS mma.sync GEMMs (both operands cp.async fp16),
// 4-stage pipeline, 1 barrier/chunk. 64x64 warp tiles.
// ---------------------------------------------------------------------------

#define Bc 8
#define Sc 2048
#define Dc 1024
#define Hc 16
#define DHc 64
#define Mc (Bc * Sc)   // 16384

__device__ float  g_Q[Mc * Dc];
__device__ float  g_K[Mc * Dc];
__device__ __half g_Qh[Mc * Dc];        // fp16 activations (reused for scaled Q)
__device__ __half g_Kh[Mc * Dc];
__device__ __half g_WQt[Dc * Dc];       // [n][k] transposed fp16 weights
__device__ __half g_WKt[Dc * Dc];
__device__ __half g_WPt[Dc * Dc];
__device__ float  g_logA[Bc * Hc * Sc];
__device__ float  g_logB[Bc * Hc * Sc];
__device__ float  g_qg[Bc * Hc * DHc];
__device__ float  g_kg[Bc * Dc];

// ===========================================================================
__device__ __forceinline__ uint32_t cvta_smem(const void* p) {
    uint32_t a;
    asm("{ .reg .u64 t; cvta.to.shared.u64 t, %1; cvt.u32.u64 %0, t; }" : "=r"(a) : "l"(p));
    return a;
}
__device__ __forceinline__ void cp16(uint32_t s, const void* g) {
    asm volatile("cp.async.cg.shared.global [%0], [%1], 16;" :: "r"(s), "l"(g));
}
__device__ __forceinline__ void cp_commit() {
    asm volatile("cp.async.commit_group;" ::: "memory");
}
template <int N>
__device__ __forceinline__ void cp_wait() {
    asm volatile("cp.async.wait_group %0;" :: "n"(N) : "memory");
}
__device__ __forceinline__ void ldmx4(uint32_t& r0, uint32_t& r1, uint32_t& r2, uint32_t& r3,
                                      uint32_t addr) {
    asm volatile("ldmatrix.sync.aligned.m8n8.x4.shared.b16 {%0,%1,%2,%3}, [%4];"
                 : "=r"(r0), "=r"(r1), "=r"(r2), "=r"(r3) : "r"(addr));
}
__device__ __forceinline__ void mma_f16(float& c0, float& c1, float& c2, float& c3,
                                        uint32_t a0, uint32_t a1, uint32_t a2, uint32_t a3,
                                        uint32_t b0, uint32_t b1) {
    asm volatile(
        "mma.sync.aligned.m16n8k16.row.col.f32.f16.f16.f32 "
        "{%0,%1,%2,%3}, {%4,%5,%6,%7}, {%8,%9}, {%0,%1,%2,%3};"
        : "+f"(c0), "+f"(c1), "+f"(c2), "+f"(c3)
        : "r"(a0), "r"(a1), "r"(a2), "r"(a3), "r"(b0), "r"(b1));
}
__device__ __forceinline__ uint32_t pack_h2(float x, float y) {
    __half2 h = __floats2half2_rn(x, y);
    return *reinterpret_cast<uint32_t*>(&h);
}

// ===========================================================================
// GEMM: C[M,N] = Ah[M,K](fp16) @ Bt[N,K](fp16)^T.  BM=BN=128, BK=32,
// 128 thr (2x2 warps, 64x64 tiles), fp16 m16n8k16, 4-stage cp.async,
// one __syncthreads per chunk.  RES=1: epilogue += resid (fp32).
// smem row stride 80B: 16B-aligned, ldmatrix conflict-free.
// ===========================================================================
#define RSTRIDE 80
#define TILEB (128 * RSTRIDE)       // 10240
#define STGB (2 * TILEB)            // 20480
#define NSTG 4
#define GSMEM (NSTG * STGB)         // 81920
#define NCH (Dc / 32)               // 32

template <int RES>
__device__ __forceinline__ void gemm_body(
    const __half* __restrict__ A, const __half* __restrict__ Bt,
    float* __restrict__ C, const float* __restrict__ resid)
{
    extern __shared__ char smem[];
    const uint32_t sb = cvta_smem(smem);
    const int tid  = threadIdx.x;
    const int wid  = tid >> 5, lane = tid & 31;
    const int g    = lane >> 2, t = lane & 3;
    const int wm   = wid >> 1, wn = wid & 1;
    const int crow = blockIdx.y * 128, ccol = blockIdx.x * 128;

    // loaders: 4 thr/row (16B fp16 each), 32 rows/pass, 4 passes
    const int lrow = tid >> 2, lseg = tid & 3;
    const __half* Ag = A  + (size_t)(crow + lrow) * Dc + lseg * 8;
    const __half* Bg = Bt + (size_t)(ccol + lrow) * Dc + lseg * 8;
    const uint32_t sA = (uint32_t)(lrow * RSTRIDE + lseg * 16);
    const uint32_t sB = (uint32_t)(TILEB + lrow * RSTRIDE + lseg * 16);

    // ldmatrix per-lane offsets
    const int ltile = lane >> 3, lr = lane & 7;
    uint32_t offA[4], offB[4];
#pragma unroll
    for (int im = 0; im < 4; im++)
        offA[im] = (uint32_t)((wm * 64 + im * 16 + (ltile & 1) * 8 + lr) * RSTRIDE
                              + (ltile >> 1) * 16);
#pragma unroll
    for (int j = 0; j < 4; j++)
        offB[j] = (uint32_t)(TILEB + (wn * 64 + j * 16 + (ltile >> 1) * 8 + lr) * RSTRIDE
                             + (ltile & 1) * 16);

    float acc[4][8][4];
#pragma unroll
    for (int i = 0; i < 4; i++)
#pragma unroll
        for (int j = 0; j < 8; j++)
#pragma unroll
            for (int k = 0; k < 4; k++) acc[i][j][k] = 0.f;

    auto issue = [&](int c) {
        uint32_t base = sb + (uint32_t)(c & (NSTG - 1)) * STGB;
        const __half* ag = Ag + c * 32;
        const __half* bg = Bg + c * 32;
#pragma unroll
        for (int p = 0; p < 4; p++) {
            cp16(base + sA + p * 32 * RSTRIDE, ag + (size_t)p * 32 * Dc);
            cp16(base + sB + p * 32 * RSTRIDE, bg + (size_t)p * 32 * Dc);
        }
        cp_commit();
    };

    issue(0); issue(1); issue(2);

    for (int c = 0; c < NCH; c++) {
        if (c + 2 < NCH)      cp_wait<2>();
        else if (c + 1 < NCH) cp_wait<1>();
        else                  cp_wait<0>();
        __syncthreads();                 // stage c visible; slot (c-1)%4 drained
        if (c + 3 < NCH) issue(c + 3);

        const uint32_t base = sb + (uint32_t)(c & (NSTG - 1)) * STGB;

#pragma unroll
        for (int kk = 0; kk < 2; kk++) {
            uint32_t a[4][4], b[8][2];
#pragma unroll
            for (int im = 0; im < 4; im++)
                ldmx4(a[im][0], a[im][1], a[im][2], a[im][3],
                      base + offA[im] + kk * 32);
#pragma unroll
            for (int j = 0; j < 4; j++) {
                uint32_t r0, r1, r2, r3;
                ldmx4(r0, r1, r2, r3, base + offB[j] + kk * 32);
                b[2 * j][0] = r0;     b[2 * j][1] = r1;
                b[2 * j + 1][0] = r2; b[2 * j + 1][1] = r3;
            }
#pragma unroll
            for (int im = 0; im < 4; im++)
#pragma unroll
                for (int in = 0; in < 8; in++)
                    mma_f16(acc[im][in][0], acc[im][in][1], acc[im][in][2], acc[im][in][3],
                            a[im][0], a[im][1], a[im][2], a[im][3],
                            b[in][0], b[in][1]);
        }
    }
    __syncthreads();

    // epilogue (fragment rows g, g+8; cols 2t, 2t+1)
#pragma unroll
    for (int im = 0; im < 4; im++) {
#pragma unroll
        for (int in = 0; in < 8; in++) {
            const int r0 = crow + wm * 64 + im * 16 + g;
            const int cc = ccol + wn * 64 + in * 8 + 2 * t;
            float2 v0 = make_float2(acc[im][in][0], acc[im][in][1]);
            float2 v1 = make_float2(acc[im][in][2], acc[im][in][3]);
            if (RES) {
                float2 q0 = *(const float2*)(resid + (size_t)r0 * Dc + cc);
                float2 q1 = *(const float2*)(resid + (size_t)(r0 + 8) * Dc + cc);
                v0.x += q0.x; v0.y += q0.y; v1.x += q1.x; v1.y += q1.y;
            }
            *(float2*)(C + (size_t)r0 * Dc + cc) = v0;
            *(float2*)(C + (size_t)(r0 + 8) * Dc + cc) = v1;
        }
    }
}

// fused Q&K projection: blockIdx.z picks the problem
__global__ __launch_bounds__(128, 2)
void gemm_qk(const __half* __restrict__ Aq, const __half* __restrict__ Ak,
             const __half* __restrict__ Bq, const __half* __restrict__ Bk,
             float* __restrict__ Cq, float* __restrict__ Ck)
{
    if (blockIdx.z == 0) gemm_body<0>(Aq, Bq, Cq, nullptr);
    else                 gemm_body<0>(Ak, Bk, Ck, nullptr);
}

__global__ __launch_bounds__(128, 2)
void gemm_out(const __half* __restrict__ A, const __half* __restrict__ Bt,
              float* __restrict__ C, const float* __restrict__ resid)
{
    gemm_body<1>(A, Bt, C, resid);
}

// ===========================================================================
// weight transpose + fp16 (3 weights in one launch via z)
// ===========================================================================
__global__ void tcvt_k(const float* __restrict__ W0, const float* __restrict__ W1,
                       const float* __restrict__ W2,
                       __half* __restrict__ T0, __half* __restrict__ T1,
                       __half* __restrict__ T2)
{
    const float* W = (blockIdx.z == 0) ? W0 : (blockIdx.z == 1) ? W1 : W2;
    __half* Wt     = (blockIdx.z == 0) ? T0 : (blockIdx.z == 1) ? T1 : T2;
    __shared__ float tbuf[32][33];
    int n0 = blockIdx.x * 32, k0 = blockIdx.y * 32;
    int tx = threadIdx.x, ty = threadIdx.y;
#pragma unroll
    for (int i = 0; i < 32; i += 8) tbuf[ty + i][tx] = W[(size_t)(k0 + ty + i) * Dc + n0 + tx];
    __syncthreads();
#pragma unroll
    for (int i = 0; i < 32; i += 8)
        Wt[(size_t)(n0 + ty + i) * Dc + k0 + tx] = __float2half_rn(tbuf[tx][ty + i]);
}

// fp32 -> fp16 elementwise (float4 granularity)
__global__ void cvth_k(const float* __restrict__ in, __half* __restrict__ out, int n4)
{
    int i = blockIdx.x * blockDim.x + threadIdx.x;
    if (i >= n4) return;
    float4 v = ((const float4*)in)[i];
    uint2 o = make_uint2(pack_h2(v.x, v.y), pack_h2(v.z, v.w));
    ((uint2*)out)[i] = o;
}

// g_Qh[m][k] = half(g_Q[m][k] * kg[b,k]),  b = m / Sc
__global__ void scaleh_k()
{
    int i = blockIdx.x * blockDim.x + threadIdx.x;   // over Mc*Dc/4
    int k4 = i & 255, m = i >> 8, b = m >> 11;
    float4 v = ((const float4*)g_Q)[i];
    float4 s = ((const float4*)g_kg)[b * 256 + k4];
    uint2 o = make_uint2(pack_h2(v.x * s.x, v.y * s.y), pack_h2(v.z * s.z, v.w * s.w));
    ((uint2*)g_Qh)[i] = o;
}

// ===========================================================================
// logitsA: one warp per 4 rows
// ===========================================================================
__global__ void logitsA_k(const float* __restrict__ Wa)
{
    int gw = (blockIdx.x * blockDim.x + threadIdx.x) >> 5;
    int lane = threadIdx.x & 31;
    int b = gw >> 9;
    int s0 = (gw << 2) & 2047;
    const float* q = g_Q + ((size_t)gw << 2) * Dc;

    float acc[4][16];
#pragma unroll
    for (int r = 0; r < 4; r++)
#pragma unroll
        for (int e = 0; e < 16; e++) acc[r][e] = 0.f;

    for (int i = 0; i < 8; i++) {
        int d4 = lane + 32 * i;
        float4 qv[4];
#pragma unroll
        for (int r = 0; r < 4; r++)
            qv[r] = reinterpret_cast<const float4*>(q + (size_t)r * Dc)[d4];
        const float4* wa = reinterpret_cast<const float4*>(Wa) + (size_t)d4 * 16;
#pragma unroll
        for (int dd = 0; dd < 4; dd++) {
            float4 w0 = wa[dd * 4 + 0], w1 = wa[dd * 4 + 1];
            float4 w2 = wa[dd * 4 + 2], w3 = wa[dd * 4 + 3];
            float qs[4];
            qs[0] = (dd == 0) ? qv[0].x : (dd == 1) ? qv[0].y : (dd == 2) ? qv[0].z : qv[0].w;
            qs[1] = (dd == 0) ? qv[1].x : (dd == 1) ? qv[1].y : (dd == 2) ? qv[1].z : qv[1].w;
            qs[2] = (dd == 0) ? qv[2].x : (dd == 1) ? qv[2].y : (dd == 2) ? qv[2].z : qv[2].w;
            qs[3] = (dd == 0) ? qv[3].x : (dd == 1) ? qv[3].y : (dd == 2) ? qv[3].z : qv[3].w;
#pragma unroll
            for (int r = 0; r < 4; r++) {
                acc[r][0]  += qs[r] * w0.x; acc[r][1]  += qs[r] * w0.y;
                acc[r][2]  += qs[r] * w0.z; acc[r][3]  += qs[r] * w0.w;
                acc[r][4]  += qs[r] * w1.x; acc[r][5]  += qs[r] * w1.y;
                acc[r][6]  += qs[r] * w1.z; acc[r][7]  += qs[r] * w1.w;
                acc[r][8]  += qs[r] * w2.x; acc[r][9]  += qs[r] * w2.y;
                acc[r][10] += qs[r] * w2.z; acc[r][11] += qs[r] * w2.w;
                acc[r][12] += qs[r] * w3.x; acc[r][13] += qs[r] * w3.y;
                acc[r][14] += qs[r] * w3.z; acc[r][15] += qs[r] * w3.w;
            }
        }
    }

#pragma unroll
    for (int e = 0; e < 16; e++) {
        float v0 = acc[0][e], v1 = acc[1][e], v2 = acc[2][e], v3 = acc[3][e];
#pragma unroll
        for (int o = 16; o; o >>= 1) {
            v0 += __shfl_xor_sync(0xffffffffu, v0, o);
            v1 += __shfl_xor_sync(0xffffffffu, v1, o);
            v2 += __shfl_xor_sync(0xffffffffu, v2, o);
            v3 += __shfl_xor_sync(0xffffffffu, v3, o);
        }
        if (lane == e) {
            float* dst = g_logA + (b * Hc + e) * Sc + s0;
            dst[0] = v0 * 0.125f; dst[1] = v1 * 0.125f;
            dst[2] = v2 * 0.125f; dst[3] = v3 * 0.125f;
        }
    }
}

// ===========================================================================
// logitsB: one warp per 4 scrambled rows
// ===========================================================================
__global__ void logitsB_k(const float* __restrict__ Wb)
{
    int gw = (blockIdx.x * blockDim.x + threadIdx.x) >> 5;
    int lane = threadIdx.x & 31;
    int b = gw >> 9;
    int spL = (gw << 2) & 2047;
    int h0 = spL >> 7;
    int s0 = (spL & 127) << 4;

    const float* qgv = g_qg + (b * Hc + h0) * DHc;
    const float* Kb  = g_K + ((size_t)(b * Sc + s0)) * Dc + h0 * DHc;

    float acc[4][16];
#pragma unroll
    for (int r = 0; r < 4; r++)
#pragma unroll
        for (int e = 0; e < 16; e++) acc[r][e] = 0.f;

    for (int i = 0; i < 32; i++) {
        int k = lane + 32 * i;
        int tt = k >> 6, j = k & 63;
        float qv = qgv[j];
        float vr[4];
#pragma unroll
        for (int r = 0; r < 4; r++)
            vr[r] = Kb[(size_t)(r * 16 + tt) * Dc + j] * qv;
        const float4* w4 = reinterpret_cast<const float4*>(Wb + k * 16);
        float4 w0 = w4[0], w1 = w4[1], w2 = w4[2], w3 = w4[3];
#pragma unroll
        for (int r = 0; r < 4; r++) {
            acc[r][0]  += vr[r] * w0.x; acc[r][1]  += vr[r] * w0.y;
            acc[r][2]  += vr[r] * w0.z; acc[r][3]  += vr[r] * w0.w;
            acc[r][4]  += vr[r] * w1.x; acc[r][5]  += vr[r] * w1.y;
            acc[r][6]  += vr[r] * w1.z; acc[r][7]  += vr[r] * w1.w;
            acc[r][8]  += vr[r] * w2.x; acc[r][9]  += vr[r] * w2.y;
            acc[r][10] += vr[r] * w2.z; acc[r][11] += vr[r] * w2.w;
            acc[r][12] += vr[r] * w3.x; acc[r][13] += vr[r] * w3.y;
            acc[r][14] += vr[r] * w3.z; acc[r][15] += vr[r] * w3.w;
        }
    }

#pragma unroll
    for (int e = 0; e < 16; e++) {
        float v0 = acc[0][e], v1 = acc[1][e], v2 = acc[2][e], v3 = acc[3][e];
#pragma unroll
        for (int o = 16; o; o >>= 1) {
            v0 += __shfl_xor_sync(0xffffffffu, v0, o);
            v1 += __shfl_xor_sync(0xffffffffu, v1, o);
            v2 += __shfl_xor_sync(0xffffffffu, v2, o);
            v3 += __shfl_xor_sync(0xffffffffu, v3, o);
        }
        if (lane == e) {
            float* dst = g_logB + (b * Hc + e) * Sc + spL;
            dst[0] = v0 * 0.125f; dst[1] = v1 * 0.125f;
            dst[2] = v2 * 0.125f; dst[3] = v3 * 0.125f;
        }
    }
}

// ===========================================================================
__global__ void pool_k(const float* __restrict__ logits, const float* __restrict__ X,
                       const float* __restrict__ qscale, float* __restrict__ out)
{
    int bh = blockIdx.x;
    int b = bh >> 4, h = bh & 15;
    const float* lg = logits + bh * Sc;

    __shared__ float sE[Sc];
    __shared__ float red[16];
    __shared__ float part[8][DHc];

    int tid = threadIdx.x, lane = tid & 31, warp = tid >> 5;

    float mx = -1e30f;
    for (int s = tid; s < Sc; s += 512) mx = fmaxf(mx, lg[s]);
#pragma unroll
    for (int o = 16; o; o >>= 1) mx = fmaxf(mx, __shfl_xor_sync(0xffffffffu, mx, o));
    if (lane == 0) red[warp] = mx;
    __syncthreads();
    mx = red[0];
#pragma unroll
    for (int i = 1; i < 16; i++) mx = fmaxf(mx, red[i]);
    __syncthreads();

    float sum = 0.f;
    for (int s = tid; s < Sc; s += 512) {
        float e = __expf(lg[s] - mx);
        sE[s] = e;
        sum += e;
    }
#pragma unroll
    for (int o = 16; o; o >>= 1) sum += __shfl_xor_sync(0xffffffffu, sum, o);
    if (lane == 0) red[warp] = sum;
    __syncthreads();
    float tot = 0.f;
#pragma unroll
    for (int i = 0; i < 16; i++) tot += red[i];
    float inv = 1.0f / tot;

    int j = tid & 63, gg = tid >> 6;
    const float* Xb = X + ((size_t)b * Sc) * Dc + h * DHc + j;
    float a0 = 0.f, a1 = 0.f, a2 = 0.f, a3 = 0.f;
    for (int s = gg; s < Sc; s += 32) {
        a0 += sE[s]      * Xb[(size_t)s * Dc];
        a1 += sE[s + 8]  * Xb[(size_t)(s + 8)  * Dc];
        a2 += sE[s + 16] * Xb[(size_t)(s + 16) * Dc];
        a3 += sE[s + 24] * Xb[(size_t)(s + 24) * Dc];
    }
    part[gg][j] = (a0 + a1) + (a2 + a3);
    __syncthreads();
    if (gg == 0) {
        float v = 0.f;
#pragma unroll
        for (int i = 0; i < 8; i++) v += part[i][j];
        v *= inv;
        if (qscale) v *= qscale[bh * DHc + j];
        out[bh * DHc + j] = v;
    }
}

// ===========================================================================
extern "C" void kernel_launch(void* const* d_in, const int* in_sizes, int n_in,
                              void* d_out, int out_size)
{
    const float* Qseq = (const float*)d_in[0];
    const float* Kseq = (const float*)d_in[1];
    const float* WQ = (const float*)d_in[3];
    const float* WK = (const float*)d_in[4];
    const float* Wa = (const float*)d_in[5];
    const float* Wb = (const float*)d_in[6];
    const float* WP = (const float*)d_in[7];
    float* out = (float*)d_out;

    float *pQ, *pK, *pLA, *pLB, *pqg, *pkg;
    __half *pQh, *pKh, *pWQ, *pWK, *pWP;
    cudaGetSymbolAddress((void**)&pQ,  g_Q);
    cudaGetSymbolAddress((void**)&pK,  g_K);
    cudaGetSymbolAddress((void**)&pQh, g_Qh);
    cudaGetSymbolAddress((void**)&pKh, g_Kh);
    cudaGetSymbolAddress((void**)&pWQ, g_WQt);
    cudaGetSymbolAddress((void**)&pWK, g_WKt);
    cudaGetSymbolAddress((void**)&pWP, g_WPt);
    cudaGetSymbolAddress((void**)&pLA, g_logA);
    cudaGetSymbolAddress((void**)&pLB, g_logB);
    cudaGetSymbolAddress((void**)&pqg, g_qg);
    cudaGetSymbolAddress((void**)&pkg, g_kg);

    cudaFuncSetAttribute(gemm_qk,  cudaFuncAttributeMaxDynamicSharedMemorySize, GSMEM);
    cudaFuncSetAttribute(gemm_out, cudaFuncAttributeMaxDynamicSharedMemorySize, GSMEM);

    const int big4 = Mc * Dc / 4;
    dim3 tg(32, 32, 3), tb(32, 8);
    dim3 ggqk(Dc / 128, Mc / 128, 2);
    dim3 gg(Dc / 128, Mc / 128);

    tcvt_k<<<tg, tb>>>(WQ, WK, WP, pWQ, pWK, pWP);                 // 1
    cvth_k<<<(big4 + 255) / 256, 256>>>(Qseq, pQh, big4);          // 2
    cvth_k<<<(big4 + 255) / 256, 256>>>(Kseq, pKh, big4);          // 3
    gemm_qk<<<ggqk, 128, GSMEM>>>(pQh, pKh, pWQ, pWK, pQ, pK);     // 4 <- profiled

    logitsA_k<<<Mc / 4 / 8, 256>>>(Wa);
    pool_k<<<Bc * Hc, 512>>>(pLA, pQ, nullptr, pqg);
    logitsB_k<<<Mc / 4 / 8, 256>>>(Wb);
    pool_k<<<Bc * Hc, 512>>>(pLB, pK, pqg, pkg);

    scaleh_k<<<big4 / 256, 256>>>();                               // g_Qh = h(g_Q * kg)
    gemm_out<<<gg, 128, GSMEM>>>(pQh, pWP, out, pQ);
}